// round 2
// baseline (speedup 1.0000x reference)
#include <cuda_runtime.h>
#include <cstdint>

#define N_NODES 100000
#define N_EDGES 1600000
#define D 128
#define R 2
#define NR (N_NODES * R)          // 200000 segments
#define NCH 384                   // [h0 | h1 | x@W_root]
#define SCAN_CHUNK 1024
#define SCAN_NB ((NR + SCAN_CHUNK - 1) / SCAN_CHUNK)   // 196

// ----------------------------- scratch (static device globals; no allocs) ---
__device__ float g_XA[(size_t)N_NODES * D];
__device__ float g_XB[(size_t)N_NODES * D];
__device__ float g_H[(size_t)N_NODES * NCH];
__device__ float g_Wcat[D * NCH];
__device__ int   g_src[N_EDGES];
__device__ int   g_dst[N_EDGES];
__device__ int   g_typ[N_EDGES];
__device__ int   g_cnt[NR];
__device__ int   g_fill[NR];
__device__ int   g_rs[NR + 1];
__device__ int   g_bsums[256];
__device__ int   g_flag[2];       // [0]: edge_index is int64, [1]: edge_type is int64
__device__ int   g_csr[N_EDGES];  // src id per (dst,rel)-sorted edge

// ----------------------------- dtype detection -----------------------------
// int64 little-endian values < 2^31 -> every odd 32-bit word is 0.
__global__ void k_detect(const unsigned int* __restrict__ ei,
                         const unsigned int* __restrict__ et) {
    __shared__ int nz_i, nz_t;
    if (threadIdx.x == 0) { nz_i = 0; nz_t = 0; }
    __syncthreads();
    for (int i = threadIdx.x; i < 512; i += blockDim.x) {
        if (ei[2 * i + 1] != 0u) atomicOr(&nz_i, 1);
        if (et[2 * i + 1] != 0u) atomicOr(&nz_t, 1);
    }
    __syncthreads();
    if (threadIdx.x == 0) {
        g_flag[0] = (nz_i == 0) ? 1 : 0;
        g_flag[1] = (nz_t == 0) ? 1 : 0;
    }
}

__global__ void k_convert(const void* __restrict__ ei, const void* __restrict__ et) {
    int i = blockIdx.x * blockDim.x + threadIdx.x;
    if (i >= N_EDGES) return;
    int s, d, t;
    if (g_flag[0]) {
        const long long* p = (const long long*)ei;
        s = (int)p[i]; d = (int)p[(size_t)N_EDGES + i];
    } else {
        const int* p = (const int*)ei;
        s = p[i]; d = p[N_EDGES + i];
    }
    if (g_flag[1]) t = (int)((const long long*)et)[i];
    else           t = ((const int*)et)[i];
    g_src[i] = s; g_dst[i] = d; g_typ[i] = t;
}

// ----------------------------- CSR build -----------------------------------
__global__ void k_zero_seg() {
    int i = blockIdx.x * blockDim.x + threadIdx.x;
    if (i < NR) { g_cnt[i] = 0; g_fill[i] = 0; }
}

__global__ void k_hist() {
    int i = blockIdx.x * blockDim.x + threadIdx.x;
    if (i >= N_EDGES) return;
    atomicAdd(&g_cnt[g_dst[i] * R + g_typ[i]], 1);
}

__global__ void k_scan1() {
    __shared__ int sh[256];
    int b = blockIdx.x, t = threadIdx.x;
    int s = 0;
    #pragma unroll
    for (int i = 0; i < 4; i++) {
        int idx = b * SCAN_CHUNK + t * 4 + i;
        if (idx < NR) s += g_cnt[idx];
    }
    sh[t] = s; __syncthreads();
    for (int off = 128; off > 0; off >>= 1) {
        if (t < off) sh[t] += sh[t + off];
        __syncthreads();
    }
    if (t == 0) g_bsums[b] = sh[0];
}

__global__ void k_scan2() {
    __shared__ int sh[256];
    int t = threadIdx.x;
    sh[t] = (t < SCAN_NB) ? g_bsums[t] : 0;
    __syncthreads();
    if (t == 0) {
        int run = 0;
        for (int i = 0; i < SCAN_NB; i++) { int c = sh[i]; sh[i] = run; run += c; }
        g_rs[NR] = N_EDGES;
    }
    __syncthreads();
    if (t < SCAN_NB) g_bsums[t] = sh[t];
}

__global__ void k_scan3() {
    __shared__ int sh[256];
    int b = blockIdx.x, t = threadIdx.x;
    int base = b * SCAN_CHUNK;
    int v[4]; int s = 0;
    #pragma unroll
    for (int i = 0; i < 4; i++) {
        int idx = base + t * 4 + i;
        v[i] = (idx < NR) ? g_cnt[idx] : 0;
        s += v[i];
    }
    sh[t] = s; __syncthreads();
    // inclusive Hillis-Steele over 256 thread totals
    for (int off = 1; off < 256; off <<= 1) {
        int cur = sh[t];
        int y = (t >= off) ? sh[t - off] : 0;
        __syncthreads();
        sh[t] = cur + y;
        __syncthreads();
    }
    int run = g_bsums[b] + sh[t] - s;   // exclusive prefix for this thread
    #pragma unroll
    for (int i = 0; i < 4; i++) {
        int idx = base + t * 4 + i;
        if (idx < NR) g_rs[idx] = run;
        run += v[i];
    }
}

__global__ void k_fill() {
    int i = blockIdx.x * blockDim.x + threadIdx.x;
    if (i >= N_EDGES) return;
    int seg = g_dst[i] * R + g_typ[i];
    int pos = atomicAdd(&g_fill[seg], 1);
    g_csr[g_rs[seg] + pos] = g_src[i];
}

// ----------------------------- feature encoder -----------------------------
// one block (128 threads) per node: x0 = concat(lrelu(des@Wd+b), ..., lrelu(cat@Wc+b))
__global__ void k_encode(const float* __restrict__ des, const float* __restrict__ twt,
                         const float* __restrict__ nump, const float* __restrict__ catp,
                         const float* __restrict__ Wd, const float* __restrict__ bd,
                         const float* __restrict__ Wt, const float* __restrict__ bt,
                         const float* __restrict__ Wn, const float* __restrict__ bn,
                         const float* __restrict__ Wc, const float* __restrict__ bc) {
    int n = blockIdx.x;
    __shared__ float sin[224];
    int t = threadIdx.x;
    if (t < 100) sin[t] = des[(size_t)n * 100 + t];
    for (int i = t; i < 100; i += 128) sin[100 + i] = twt[(size_t)n * 100 + i];
    if (t < 6)  sin[200 + t] = nump[(size_t)n * 6 + t];
    if (t < 11) sin[206 + t] = catp[(size_t)n * 11 + t];
    __syncthreads();

    int q = t >> 5, j = t & 31;
    const float* W; const float* b; const float* in; int fan;
    if (q == 0)      { W = Wd; b = bd; in = sin;       fan = 100; }
    else if (q == 1) { W = Wt; b = bt; in = sin + 100; fan = 100; }
    else if (q == 2) { W = Wn; b = bn; in = sin + 200; fan = 6;   }
    else             { W = Wc; b = bc; in = sin + 206; fan = 11;  }
    float acc = b[j];
    for (int k = 0; k < fan; k++) acc = fmaf(in[k], W[k * 32 + j], acc);
    acc = acc > 0.f ? acc : 0.01f * acc;
    g_XA[(size_t)n * D + t] = acc;
}

// ----------------------------- weight pack: [Wrel0|Wrel1|Wroot] -> [128,384]
__global__ void k_pack(const float* __restrict__ Wrel, const float* __restrict__ Wroot) {
    int i = blockIdx.x * blockDim.x + threadIdx.x;
    if (i >= D * NCH) return;
    int d = i / NCH, c = i % NCH;
    float v;
    if (c < 256) v = Wrel[(c >> 7) * (D * D) + d * D + (c & 127)];
    else         v = Wroot[d * D + (c - 256)];
    g_Wcat[i] = v;
}

// ----------------------------- SIMT fp32 GEMM: C[M,NC] = A[M,128] @ B[128,NC]
// BM=64, BN=64, BK=16, 256 threads, 4x4 per thread. Optional bias + leakyrelu.
__global__ void k_gemm(const float* __restrict__ A, const float* __restrict__ B,
                       float* __restrict__ C, int M, int NC,
                       const float* __restrict__ bias, int act) {
    __shared__ __align__(16) float As[16][64];
    __shared__ __align__(16) float Bs[16][64];
    int tid = threadIdx.x;
    int tx = tid & 15, ty = tid >> 4;
    int bm = blockIdx.y * 64;
    int bn = blockIdx.x * 64;

    float acc[4][4] = {};

    int ar  = tid >> 2;          // 0..63 (A row within tile)
    int ac4 = (tid & 3) * 4;     // 0,4,8,12
    int br  = tid >> 4;          // 0..15 (B row within k-slab)
    int bc4 = (tid & 15) * 4;
    int arow = bm + ar;

    for (int kk = 0; kk < 128; kk += 16) {
        float4 a = make_float4(0.f, 0.f, 0.f, 0.f);
        if (arow < M) a = *(const float4*)(A + (size_t)arow * 128 + kk + ac4);
        As[ac4 + 0][ar] = a.x; As[ac4 + 1][ar] = a.y;
        As[ac4 + 2][ar] = a.z; As[ac4 + 3][ar] = a.w;
        float4 bv = *(const float4*)(B + (size_t)(kk + br) * NC + bn + bc4);
        *(float4*)&Bs[br][bc4] = bv;
        __syncthreads();
        #pragma unroll
        for (int k = 0; k < 16; k++) {
            float4 av = *(const float4*)&As[k][ty * 4];
            float4 bw = *(const float4*)&Bs[k][tx * 4];
            acc[0][0] = fmaf(av.x, bw.x, acc[0][0]);
            acc[0][1] = fmaf(av.x, bw.y, acc[0][1]);
            acc[0][2] = fmaf(av.x, bw.z, acc[0][2]);
            acc[0][3] = fmaf(av.x, bw.w, acc[0][3]);
            acc[1][0] = fmaf(av.y, bw.x, acc[1][0]);
            acc[1][1] = fmaf(av.y, bw.y, acc[1][1]);
            acc[1][2] = fmaf(av.y, bw.z, acc[1][2]);
            acc[1][3] = fmaf(av.y, bw.w, acc[1][3]);
            acc[2][0] = fmaf(av.z, bw.x, acc[2][0]);
            acc[2][1] = fmaf(av.z, bw.y, acc[2][1]);
            acc[2][2] = fmaf(av.z, bw.z, acc[2][2]);
            acc[2][3] = fmaf(av.z, bw.w, acc[2][3]);
            acc[3][0] = fmaf(av.w, bw.x, acc[3][0]);
            acc[3][1] = fmaf(av.w, bw.y, acc[3][1]);
            acc[3][2] = fmaf(av.w, bw.z, acc[3][2]);
            acc[3][3] = fmaf(av.w, bw.w, acc[3][3]);
        }
        __syncthreads();
    }

    #pragma unroll
    for (int i = 0; i < 4; i++) {
        int r = bm + ty * 4 + i;
        if (r >= M) continue;
        int c0 = bn + tx * 4;
        float4 v = make_float4(acc[i][0], acc[i][1], acc[i][2], acc[i][3]);
        if (bias) {
            v.x += bias[c0 + 0]; v.y += bias[c0 + 1];
            v.z += bias[c0 + 2]; v.w += bias[c0 + 3];
        }
        if (act) {
            v.x = v.x > 0.f ? v.x : 0.01f * v.x;
            v.y = v.y > 0.f ? v.y : 0.01f * v.y;
            v.z = v.z > 0.f ? v.z : 0.01f * v.z;
            v.w = v.w > 0.f ? v.w : 0.01f * v.w;
        }
        *(float4*)(C + (size_t)r * NC + c0) = v;
    }
}

// ----------------------------- RGCN aggregation ----------------------------
// one warp per node; H row = [h0(128) | h1(128) | x@Wroot(128)]
__global__ void k_agg(const float* __restrict__ H, float* __restrict__ Xout,
                      const float* __restrict__ b_rgcn) {
    int warp = (blockIdx.x * blockDim.x + threadIdx.x) >> 5;
    int lane = threadIdx.x & 31;
    if (warp >= N_NODES) return;
    int n = warp;

    float4 acc = ((const float4*)(H + (size_t)n * NCH + 256))[lane]; // root term
    float4 bb = ((const float4*)b_rgcn)[lane];
    acc.x += bb.x; acc.y += bb.y; acc.z += bb.z; acc.w += bb.w;

    #pragma unroll
    for (int rel = 0; rel < R; rel++) {
        int s = g_rs[n * R + rel];
        int e = g_rs[n * R + rel + 1];
        float4 sum = make_float4(0.f, 0.f, 0.f, 0.f);
        for (int i = s; i < e; i++) {
            int src = g_csr[i];
            float4 v = ((const float4*)(H + (size_t)src * NCH + rel * D))[lane];
            sum.x += v.x; sum.y += v.y; sum.z += v.z; sum.w += v.w;
        }
        float inv = (e > s) ? 1.0f / (float)(e - s) : 0.0f;
        acc.x = fmaf(sum.x, inv, acc.x);
        acc.y = fmaf(sum.y, inv, acc.y);
        acc.z = fmaf(sum.z, inv, acc.z);
        acc.w = fmaf(sum.w, inv, acc.w);
    }
    ((float4*)(Xout + (size_t)n * D))[lane] = acc;
}

// ----------------------------- final projection to 2 classes ---------------
__global__ void k_final(const float* __restrict__ Y, const float* __restrict__ Wo2,
                        const float* __restrict__ bo2, float* __restrict__ out) {
    int warp = (blockIdx.x * blockDim.x + threadIdx.x) >> 5;
    int lane = threadIdx.x & 31;
    if (warp >= N_NODES) return;
    float4 y = ((const float4*)(Y + (size_t)warp * D))[lane];
    int k0 = lane * 4;
    float s0 = y.x * Wo2[(k0 + 0) * 2 + 0] + y.y * Wo2[(k0 + 1) * 2 + 0]
             + y.z * Wo2[(k0 + 2) * 2 + 0] + y.w * Wo2[(k0 + 3) * 2 + 0];
    float s1 = y.x * Wo2[(k0 + 0) * 2 + 1] + y.y * Wo2[(k0 + 1) * 2 + 1]
             + y.z * Wo2[(k0 + 2) * 2 + 1] + y.w * Wo2[(k0 + 3) * 2 + 1];
    #pragma unroll
    for (int off = 16; off > 0; off >>= 1) {
        s0 += __shfl_down_sync(0xFFFFFFFFu, s0, off);
        s1 += __shfl_down_sync(0xFFFFFFFFu, s1, off);
    }
    if (lane == 0) {
        out[(size_t)warp * 2 + 0] = s0 + bo2[0];
        out[(size_t)warp * 2 + 1] = s1 + bo2[1];
    }
}

// ----------------------------- launch --------------------------------------
extern "C" void kernel_launch(void* const* d_in, const int* in_sizes, int n_in,
                              void* d_out, int out_size) {
    const float* des   = (const float*)d_in[0];
    const float* twt   = (const float*)d_in[1];
    const float* nump  = (const float*)d_in[2];
    const float* catp  = (const float*)d_in[3];
    const void*  ei    = d_in[4];
    const void*  et    = d_in[5];
    const float* Wd    = (const float*)d_in[6];
    const float* bd    = (const float*)d_in[7];
    const float* Wt    = (const float*)d_in[8];
    const float* bt    = (const float*)d_in[9];
    const float* Wn    = (const float*)d_in[10];
    const float* bn    = (const float*)d_in[11];
    const float* Wc    = (const float*)d_in[12];
    const float* bc    = (const float*)d_in[13];
    const float* W_in  = (const float*)d_in[14];
    const float* b_in  = (const float*)d_in[15];
    const float* W_rel = (const float*)d_in[16];
    const float* W_root= (const float*)d_in[17];
    const float* b_rg  = (const float*)d_in[18];
    const float* W_o1  = (const float*)d_in[19];
    const float* b_o1  = (const float*)d_in[20];
    const float* W_o2  = (const float*)d_in[21];
    const float* b_o2  = (const float*)d_in[22];
    float* out = (float*)d_out;

    float *XA, *XB, *H;
    cudaGetSymbolAddress((void**)&XA, g_XA);
    cudaGetSymbolAddress((void**)&XB, g_XB);
    cudaGetSymbolAddress((void**)&H,  g_H);
    float* Wcat;
    cudaGetSymbolAddress((void**)&Wcat, g_Wcat);

    const int TB = 256;
    int ceb = (N_EDGES + TB - 1) / TB;

    // --- edge preprocessing / CSR build ---
    k_detect<<<1, 64>>>((const unsigned int*)ei, (const unsigned int*)et);
    k_convert<<<ceb, TB>>>(ei, et);
    k_zero_seg<<<(NR + TB - 1) / TB, TB>>>();
    k_hist<<<ceb, TB>>>();
    k_scan1<<<SCAN_NB, 256>>>();
    k_scan2<<<1, 256>>>();
    k_scan3<<<SCAN_NB, 256>>>();
    k_fill<<<ceb, TB>>>();

    // --- feature encoding + input linear ---
    k_encode<<<N_NODES, 128>>>(des, twt, nump, catp, Wd, bd, Wt, bt, Wn, bn, Wc, bc);
    k_pack<<<(D * NCH + TB - 1) / TB, TB>>>(W_rel, W_root);

    dim3 g128(128 / 64, (N_NODES + 63) / 64);
    dim3 g384(NCH / 64, (N_NODES + 63) / 64);

    // XB = lrelu(XA @ W_in + b_in)
    k_gemm<<<g128, 256>>>(XA, W_in, XB, N_NODES, 128, b_in, 1);

    // RGCN layer 1: H = XB @ [Wrel0|Wrel1|Wroot]; XA = agg(H)
    k_gemm<<<g384, 256>>>(XB, Wcat, H, N_NODES, NCH, nullptr, 0);
    k_agg<<<(N_NODES * 32 + TB - 1) / TB, TB>>>(H, XA, b_rg);

    // RGCN layer 2: H = XA @ Wcat; XB = agg(H)
    k_gemm<<<g384, 256>>>(XA, Wcat, H, N_NODES, NCH, nullptr, 0);
    k_agg<<<(N_NODES * 32 + TB - 1) / TB, TB>>>(H, XB, b_rg);

    // XA = lrelu(XB @ W_o1 + b_o1); out = XA @ W_o2 + b_o2
    k_gemm<<<g128, 256>>>(XB, W_o1, XA, N_NODES, 128, b_o1, 1);
    k_final<<<(N_NODES * 32 + TB - 1) / TB, TB>>>(XA, W_o2, b_o2, out);
}

// round 5
// speedup vs baseline: 1.3263x; 1.3263x over previous
#include <cuda_runtime.h>
#include <cstdint>

#define N_NODES 100000
#define N_EDGES 1600000
#define D 128
#define R 2
#define NR (N_NODES * R)          // 200000 segments
#define SCAN_CHUNK 1024
#define SCAN_NB ((NR + SCAN_CHUNK - 1) / SCAN_CHUNK)   // 196

// ----------------------------- scratch (static device globals; no allocs) ---
__device__ float g_XA[(size_t)N_NODES * D];
__device__ float g_XB[(size_t)N_NODES * D];
__device__ float g_M[(size_t)N_NODES * 256];   // [mean_rel0 | mean_rel1]
__device__ float g_WinT[D * D];                // W_in^T  [n][k]
__device__ float g_Wo1T[D * D];                // W_o1^T  [n][k]
__device__ float g_WstkT[D * 384];             // [n][ Wrel0col | Wrel1col | Wrootcol ]
__device__ int   g_src[N_EDGES];
__device__ int   g_dst[N_EDGES];
__device__ int   g_typ[N_EDGES];
__device__ int   g_cnt[NR];
__device__ int   g_fill[NR];
__device__ int   g_rs[NR + 1];
__device__ int   g_bsums[256];
__device__ int   g_flag[2];
__device__ int   g_csr[N_EDGES];

// ----------------------------- dtype detection -----------------------------
__global__ void k_detect(const unsigned int* __restrict__ ei,
                         const unsigned int* __restrict__ et) {
    __shared__ int nz_i, nz_t;
    if (threadIdx.x == 0) { nz_i = 0; nz_t = 0; }
    __syncthreads();
    for (int i = threadIdx.x; i < 512; i += blockDim.x) {
        if (ei[2 * i + 1] != 0u) atomicOr(&nz_i, 1);
        if (et[2 * i + 1] != 0u) atomicOr(&nz_t, 1);
    }
    __syncthreads();
    if (threadIdx.x == 0) {
        g_flag[0] = (nz_i == 0) ? 1 : 0;
        g_flag[1] = (nz_t == 0) ? 1 : 0;
    }
}

__global__ void k_convert(const void* __restrict__ ei, const void* __restrict__ et) {
    int i = blockIdx.x * blockDim.x + threadIdx.x;
    if (i >= N_EDGES) return;
    int s, d, t;
    if (g_flag[0]) {
        const long long* p = (const long long*)ei;
        s = (int)p[i]; d = (int)p[(size_t)N_EDGES + i];
    } else {
        const int* p = (const int*)ei;
        s = p[i]; d = p[N_EDGES + i];
    }
    if (g_flag[1]) t = (int)((const long long*)et)[i];
    else           t = ((const int*)et)[i];
    g_src[i] = s; g_dst[i] = d; g_typ[i] = t;
}

// ----------------------------- CSR build -----------------------------------
__global__ void k_zero_seg() {
    int i = blockIdx.x * blockDim.x + threadIdx.x;
    if (i < NR) { g_cnt[i] = 0; g_fill[i] = 0; }
}

__global__ void k_hist() {
    int i = blockIdx.x * blockDim.x + threadIdx.x;
    if (i >= N_EDGES) return;
    atomicAdd(&g_cnt[g_dst[i] * R + g_typ[i]], 1);
}

__global__ void k_scan1() {
    __shared__ int sh[256];
    int b = blockIdx.x, t = threadIdx.x;
    int s = 0;
    #pragma unroll
    for (int i = 0; i < 4; i++) {
        int idx = b * SCAN_CHUNK + t * 4 + i;
        if (idx < NR) s += g_cnt[idx];
    }
    sh[t] = s; __syncthreads();
    for (int off = 128; off > 0; off >>= 1) {
        if (t < off) sh[t] += sh[t + off];
        __syncthreads();
    }
    if (t == 0) g_bsums[b] = sh[0];
}

__global__ void k_scan2() {
    __shared__ int sh[256];
    int t = threadIdx.x;
    sh[t] = (t < SCAN_NB) ? g_bsums[t] : 0;
    __syncthreads();
    if (t == 0) {
        int run = 0;
        for (int i = 0; i < SCAN_NB; i++) { int c = sh[i]; sh[i] = run; run += c; }
        g_rs[NR] = N_EDGES;
    }
    __syncthreads();
    if (t < SCAN_NB) g_bsums[t] = sh[t];
}

__global__ void k_scan3() {
    __shared__ int sh[256];
    int b = blockIdx.x, t = threadIdx.x;
    int base = b * SCAN_CHUNK;
    int v[4]; int s = 0;
    #pragma unroll
    for (int i = 0; i < 4; i++) {
        int idx = base + t * 4 + i;
        v[i] = (idx < NR) ? g_cnt[idx] : 0;
        s += v[i];
    }
    sh[t] = s; __syncthreads();
    for (int off = 1; off < 256; off <<= 1) {
        int cur = sh[t];
        int y = (t >= off) ? sh[t - off] : 0;
        __syncthreads();
        sh[t] = cur + y;
        __syncthreads();
    }
    int run = g_bsums[b] + sh[t] - s;
    #pragma unroll
    for (int i = 0; i < 4; i++) {
        int idx = base + t * 4 + i;
        if (idx < NR) g_rs[idx] = run;
        run += v[i];
    }
}

__global__ void k_fill() {
    int i = blockIdx.x * blockDim.x + threadIdx.x;
    if (i >= N_EDGES) return;
    int seg = g_dst[i] * R + g_typ[i];
    int pos = atomicAdd(&g_fill[seg], 1);
    g_csr[g_rs[seg] + pos] = g_src[i];
}

// ----------------------------- feature encoder -----------------------------
__global__ void k_encode(const float* __restrict__ des, const float* __restrict__ twt,
                         const float* __restrict__ nump, const float* __restrict__ catp,
                         const float* __restrict__ Wd, const float* __restrict__ bd,
                         const float* __restrict__ Wt, const float* __restrict__ bt,
                         const float* __restrict__ Wn, const float* __restrict__ bn,
                         const float* __restrict__ Wc, const float* __restrict__ bc) {
    int n = blockIdx.x;
    __shared__ float sin[224];
    int t = threadIdx.x;
    if (t < 100) sin[t] = des[(size_t)n * 100 + t];
    for (int i = t; i < 100; i += 128) sin[100 + i] = twt[(size_t)n * 100 + i];
    if (t < 6)  sin[200 + t] = nump[(size_t)n * 6 + t];
    if (t < 11) sin[206 + t] = catp[(size_t)n * 11 + t];
    __syncthreads();

    int q = t >> 5, j = t & 31;
    const float* W; const float* b; const float* in; int fan;
    if (q == 0)      { W = Wd; b = bd; in = sin;       fan = 100; }
    else if (q == 1) { W = Wt; b = bt; in = sin + 100; fan = 100; }
    else if (q == 2) { W = Wn; b = bn; in = sin + 200; fan = 6;   }
    else             { W = Wc; b = bc; in = sin + 206; fan = 11;  }
    float acc = b[j];
    for (int k = 0; k < fan; k++) acc = fmaf(in[k], W[k * 32 + j], acc);
    acc = acc > 0.f ? acc : 0.01f * acc;
    g_XA[(size_t)n * D + t] = acc;
}

// ----------------------------- transpose pack: dst[n*ldD + off + k] = src[k*N + n]
__global__ void k_packT(const float* __restrict__ src, float* __restrict__ dst,
                        int K, int N, int ldD, int off) {
    int i = blockIdx.x * blockDim.x + threadIdx.x;
    if (i >= K * N) return;
    int k = i / N, n = i % N;
    dst[(size_t)n * ldD + off + k] = src[i];
}

// ----------------------------- 3xTF32 mma.sync GEMM ------------------------
// C[M,128] = A[M,kTot] @ Bt[128,kTot]^T + bias (optional lrelu), fp32 accuracy
// via 3xTF32: x = xh + xl; x*y ~= xh*yh + xh*yl + xl*yh.
// A = A1 rows for k<kSplit else A2 (concat along K). 256 threads, tile 128x128,
// 8 warps as 4(m) x 2(n), each warp 32x64. K-slabs of 32.

#define LDS 36   // padded row stride in 4B words (conflict-free frag loads)

__device__ __forceinline__ unsigned f2tf(float x) {
    unsigned r; asm("cvt.rna.tf32.f32 %0, %1;" : "=r"(r) : "f"(x)); return r;
}

__device__ __forceinline__ void mma_tf32(float* c, const unsigned* a,
                                         unsigned b0, unsigned b1) {
    asm volatile(
        "mma.sync.aligned.m16n8k8.row.col.f32.tf32.tf32.f32 "
        "{%0,%1,%2,%3}, {%4,%5,%6,%7}, {%8,%9}, {%0,%1,%2,%3};"
        : "+f"(c[0]), "+f"(c[1]), "+f"(c[2]), "+f"(c[3])
        : "r"(a[0]), "r"(a[1]), "r"(a[2]), "r"(a[3]), "r"(b0), "r"(b1));
}

__global__ __launch_bounds__(256) void k_gemm_tc(
    const float* __restrict__ A1, int ldA1,
    const float* __restrict__ A2, int ldA2,
    int kSplit, int kTot,
    const float* __restrict__ Bt,
    float* __restrict__ C, int M,
    const float* __restrict__ bias, int act)
{
    extern __shared__ unsigned smem[];
    unsigned* sAh = smem;                  // 128*LDS
    unsigned* sAl = sAh + 128 * LDS;
    unsigned* sBh = sAl + 128 * LDS;
    unsigned* sBl = sBh + 128 * LDS;

    int tid = threadIdx.x;
    int wid = tid >> 5, lane = tid & 31;
    int gid = lane >> 2, tig = lane & 3;
    int warp_m = wid & 3, warp_n = wid >> 2;
    int bm = blockIdx.x * 128;

    int srow = tid >> 1;          // staging row 0..127
    int shalf = tid & 1;          // which 16-wide half of the 32-slab
    int arow = bm + srow; if (arow > M - 1) arow = M - 1;

    float acc[2][8][4];
    #pragma unroll
    for (int i = 0; i < 2; i++)
        #pragma unroll
        for (int j = 0; j < 8; j++)
            #pragma unroll
            for (int q = 0; q < 4; q++) acc[i][j][q] = 0.f;

    int nSlab = kTot >> 5;
    for (int s = 0; s < nSlab; s++) {
        int k0 = s << 5;
        // ---- stage A slab (hi/lo) ----
        const float* asrc = (k0 < kSplit)
            ? A1 + (size_t)arow * ldA1 + k0 + shalf * 16
            : A2 + (size_t)arow * ldA2 + (k0 - kSplit) + shalf * 16;
        #pragma unroll
        for (int j = 0; j < 4; j++) {
            float4 v = *(const float4*)(asrc + j * 4);
            unsigned hx = f2tf(v.x), hy = f2tf(v.y), hz = f2tf(v.z), hw = f2tf(v.w);
            unsigned lx = f2tf(v.x - __uint_as_float(hx));
            unsigned ly = f2tf(v.y - __uint_as_float(hy));
            unsigned lz = f2tf(v.z - __uint_as_float(hz));
            unsigned lw = f2tf(v.w - __uint_as_float(hw));
            int o = srow * LDS + shalf * 16 + j * 4;
            *(uint4*)(sAh + o) = make_uint4(hx, hy, hz, hw);
            *(uint4*)(sAl + o) = make_uint4(lx, ly, lz, lw);
        }
        // ---- stage B slab (hi/lo) ----
        const float* bsrc = Bt + (size_t)srow * kTot + k0 + shalf * 16;
        #pragma unroll
        for (int j = 0; j < 4; j++) {
            float4 v = *(const float4*)(bsrc + j * 4);
            unsigned hx = f2tf(v.x), hy = f2tf(v.y), hz = f2tf(v.z), hw = f2tf(v.w);
            unsigned lx = f2tf(v.x - __uint_as_float(hx));
            unsigned ly = f2tf(v.y - __uint_as_float(hy));
            unsigned lz = f2tf(v.z - __uint_as_float(hz));
            unsigned lw = f2tf(v.w - __uint_as_float(hw));
            int o = srow * LDS + shalf * 16 + j * 4;
            *(uint4*)(sBh + o) = make_uint4(hx, hy, hz, hw);
            *(uint4*)(sBl + o) = make_uint4(lx, ly, lz, lw);
        }
        __syncthreads();

        // ---- compute ----
        #pragma unroll
        for (int kk = 0; kk < 4; kk++) {
            int kk8 = kk << 3;
            unsigned ah[2][4], al[2][4];
            #pragma unroll
            for (int mf = 0; mf < 2; mf++) {
                int r0 = (warp_m * 32 + mf * 16 + gid) * LDS + kk8 + tig;
                int r1 = r0 + 8 * LDS;
                ah[mf][0] = sAh[r0]; ah[mf][1] = sAh[r1];
                ah[mf][2] = sAh[r0 + 4]; ah[mf][3] = sAh[r1 + 4];
                al[mf][0] = sAl[r0]; al[mf][1] = sAl[r1];
                al[mf][2] = sAl[r0 + 4]; al[mf][3] = sAl[r1 + 4];
            }
            #pragma unroll
            for (int nf = 0; nf < 8; nf++) {
                int nb = (warp_n * 64 + nf * 8 + gid) * LDS + kk8 + tig;
                unsigned bh0 = sBh[nb], bh1 = sBh[nb + 4];
                unsigned bl0 = sBl[nb], bl1 = sBl[nb + 4];
                #pragma unroll
                for (int mf = 0; mf < 2; mf++) {
                    mma_tf32(acc[mf][nf], ah[mf], bh0, bh1);
                    mma_tf32(acc[mf][nf], al[mf], bh0, bh1);
                    mma_tf32(acc[mf][nf], ah[mf], bl0, bl1);
                }
            }
        }
        __syncthreads();
    }

    // ---- epilogue ----
    #pragma unroll
    for (int mf = 0; mf < 2; mf++) {
        int r0 = bm + warp_m * 32 + mf * 16 + gid;
        int r1 = r0 + 8;
        #pragma unroll
        for (int nf = 0; nf < 8; nf++) {
            int c = warp_n * 64 + nf * 8 + tig * 2;
            float b0 = bias[c], b1 = bias[c + 1];
            float v0 = acc[mf][nf][0] + b0, v1 = acc[mf][nf][1] + b1;
            float v2 = acc[mf][nf][2] + b0, v3 = acc[mf][nf][3] + b1;
            if (act) {
                v0 = v0 > 0.f ? v0 : 0.01f * v0;
                v1 = v1 > 0.f ? v1 : 0.01f * v1;
                v2 = v2 > 0.f ? v2 : 0.01f * v2;
                v3 = v3 > 0.f ? v3 : 0.01f * v3;
            }
            if (r0 < M) *(float2*)(C + (size_t)r0 * 128 + c) = make_float2(v0, v1);
            if (r1 < M) *(float2*)(C + (size_t)r1 * 128 + c) = make_float2(v2, v3);
        }
    }
}

// ----------------------------- aggregation (mean per (node,rel) from X) ----
__global__ void k_agg2(const float* __restrict__ X, float* __restrict__ Mout) {
    int w = (blockIdx.x * blockDim.x + threadIdx.x) >> 5;
    if (w >= NR) return;
    int lane = threadIdx.x & 31;
    int n = w >> 1, rel = w & 1;
    int s = g_rs[w], e = g_rs[w + 1];
    float4 sum = make_float4(0.f, 0.f, 0.f, 0.f);
    int i = s;
    for (; i + 4 <= e; i += 4) {
        int i0 = g_csr[i], i1 = g_csr[i + 1], i2 = g_csr[i + 2], i3 = g_csr[i + 3];
        float4 a = ((const float4*)(X + (size_t)i0 * D))[lane];
        float4 b = ((const float4*)(X + (size_t)i1 * D))[lane];
        float4 c = ((const float4*)(X + (size_t)i2 * D))[lane];
        float4 d = ((const float4*)(X + (size_t)i3 * D))[lane];
        sum.x += a.x + b.x + c.x + d.x;
        sum.y += a.y + b.y + c.y + d.y;
        sum.z += a.z + b.z + c.z + d.z;
        sum.w += a.w + b.w + c.w + d.w;
    }
    for (; i < e; i++) {
        float4 a = ((const float4*)(X + (size_t)g_csr[i] * D))[lane];
        sum.x += a.x; sum.y += a.y; sum.z += a.z; sum.w += a.w;
    }
    float inv = (e > s) ? 1.0f / (float)(e - s) : 0.0f;
    sum.x *= inv; sum.y *= inv; sum.z *= inv; sum.w *= inv;
    ((float4*)(Mout + (size_t)n * 256 + rel * D))[lane] = sum;
}

// ----------------------------- final projection to 2 classes ---------------
__global__ void k_final(const float* __restrict__ Y, const float* __restrict__ Wo2,
                        const float* __restrict__ bo2, float* __restrict__ out) {
    int warp = (blockIdx.x * blockDim.x + threadIdx.x) >> 5;
    int lane = threadIdx.x & 31;
    if (warp >= N_NODES) return;
    float4 y = ((const float4*)(Y + (size_t)warp * D))[lane];
    int k0 = lane * 4;
    float s0 = y.x * Wo2[(k0 + 0) * 2 + 0] + y.y * Wo2[(k0 + 1) * 2 + 0]
             + y.z * Wo2[(k0 + 2) * 2 + 0] + y.w * Wo2[(k0 + 3) * 2 + 0];
    float s1 = y.x * Wo2[(k0 + 0) * 2 + 1] + y.y * Wo2[(k0 + 1) * 2 + 1]
             + y.z * Wo2[(k0 + 2) * 2 + 1] + y.w * Wo2[(k0 + 3) * 2 + 1];
    #pragma unroll
    for (int off = 16; off > 0; off >>= 1) {
        s0 += __shfl_down_sync(0xFFFFFFFFu, s0, off);
        s1 += __shfl_down_sync(0xFFFFFFFFu, s1, off);
    }
    if (lane == 0) {
        out[(size_t)warp * 2 + 0] = s0 + bo2[0];
        out[(size_t)warp * 2 + 1] = s1 + bo2[1];
    }
}

// ----------------------------- launch --------------------------------------
extern "C" void kernel_launch(void* const* d_in, const int* in_sizes, int n_in,
                              void* d_out, int out_size) {
    const float* des   = (const float*)d_in[0];
    const float* twt   = (const float*)d_in[1];
    const float* nump  = (const float*)d_in[2];
    const float* catp  = (const float*)d_in[3];
    const void*  ei    = d_in[4];
    const void*  et    = d_in[5];
    const float* Wd    = (const float*)d_in[6];
    const float* bd    = (const float*)d_in[7];
    const float* Wt    = (const float*)d_in[8];
    const float* bt    = (const float*)d_in[9];
    const float* Wn    = (const float*)d_in[10];
    const float* bn    = (const float*)d_in[11];
    const float* Wc    = (const float*)d_in[12];
    const float* bc    = (const float*)d_in[13];
    const float* W_in  = (const float*)d_in[14];
    const float* b_in  = (const float*)d_in[15];
    const float* W_rel = (const float*)d_in[16];
    const float* W_root= (const float*)d_in[17];
    const float* b_rg  = (const float*)d_in[18];
    const float* W_o1  = (const float*)d_in[19];
    const float* b_o1  = (const float*)d_in[20];
    const float* W_o2  = (const float*)d_in[21];
    const float* b_o2  = (const float*)d_in[22];
    float* out = (float*)d_out;

    float *XA, *XB, *Mg, *WinT, *Wo1T, *WstkT;
    cudaGetSymbolAddress((void**)&XA, g_XA);
    cudaGetSymbolAddress((void**)&XB, g_XB);
    cudaGetSymbolAddress((void**)&Mg, g_M);
    cudaGetSymbolAddress((void**)&WinT, g_WinT);
    cudaGetSymbolAddress((void**)&Wo1T, g_Wo1T);
    cudaGetSymbolAddress((void**)&WstkT, g_WstkT);

    const int SMEM_BYTES = 4 * 128 * LDS * 4;   // 73728
    cudaFuncSetAttribute(k_gemm_tc, cudaFuncAttributeMaxDynamicSharedMemorySize, SMEM_BYTES);

    const int TB = 256;
    int ceb = (N_EDGES + TB - 1) / TB;

    // --- edge preprocessing / CSR build ---
    k_detect<<<1, 64>>>((const unsigned int*)ei, (const unsigned int*)et);
    k_convert<<<ceb, TB>>>(ei, et);
    k_zero_seg<<<(NR + TB - 1) / TB, TB>>>();
    k_hist<<<ceb, TB>>>();
    k_scan1<<<SCAN_NB, 256>>>();
    k_scan2<<<1, 256>>>();
    k_scan3<<<SCAN_NB, 256>>>();
    k_fill<<<ceb, TB>>>();

    // --- feature encoding + weight packing ---
    k_encode<<<N_NODES, 128>>>(des, twt, nump, catp, Wd, bd, Wt, bt, Wn, bn, Wc, bc);
    k_packT<<<64, 256>>>(W_in,           WinT,  128, 128, 128, 0);
    k_packT<<<64, 256>>>(W_o1,           Wo1T,  128, 128, 128, 0);
    k_packT<<<64, 256>>>(W_rel,          WstkT, 128, 128, 384, 0);
    k_packT<<<64, 256>>>(W_rel + 16384,  WstkT, 128, 128, 384, 128);
    k_packT<<<64, 256>>>(W_root,         WstkT, 128, 128, 384, 256);

    int gGemm = (N_NODES + 127) / 128;      // 782
    int gAgg  = (NR * 32 + TB - 1) / TB;    // 25000

    // x1 = lrelu(x0 @ W_in + b_in)
    k_gemm_tc<<<gGemm, 256, SMEM_BYTES>>>(XA, 128, XA, 128, 128, 128, WinT, XB, N_NODES, b_in, 1);

    // RGCN layer 1: M = means(XB); XA = [M|XB] @ WstkT^T + b_rg
    k_agg2<<<gAgg, TB>>>(XB, Mg);
    k_gemm_tc<<<gGemm, 256, SMEM_BYTES>>>(Mg, 256, XB, 128, 256, 384, WstkT, XA, N_NODES, b_rg, 0);

    // RGCN layer 2: M = means(XA); XB = [M|XA] @ WstkT^T + b_rg
    k_agg2<<<gAgg, TB>>>(XA, Mg);
    k_gemm_tc<<<gGemm, 256, SMEM_BYTES>>>(Mg, 256, XA, 128, 256, 384, WstkT, XB, N_NODES, b_rg, 0);

    // x4 = lrelu(x3 @ W_o1 + b_o1); out = x4 @ W_o2 + b_o2
    k_gemm_tc<<<gGemm, 256, SMEM_BYTES>>>(XB, 128, XB, 128, 128, 128, Wo1T, XA, N_NODES, b_o1, 1);
    k_final<<<(N_NODES * 32 + TB - 1) / TB, TB>>>(XA, W_o2, b_o2, out);
}

// round 6
// speedup vs baseline: 1.7743x; 1.3378x over previous
#include <cuda_runtime.h>
#include <cstdint>

#define N_NODES 100000
#define N_EDGES 1600000
#define D 128
#define R 2
#define NR (N_NODES * R)          // 200000 segments
#define SCAN_CHUNK 1024
#define SCAN_NB ((NR + SCAN_CHUNK - 1) / SCAN_CHUNK)   // 196

// ----------------------------- scratch (static device globals; no allocs) ---
__device__ float g_XA[(size_t)N_NODES * D];
__device__ float g_XB[(size_t)N_NODES * D];
__device__ float g_M[(size_t)N_NODES * 256];   // [mean_rel0 | mean_rel1]
__device__ float g_WinT[D * D];                // W_in^T  [n][k]
__device__ float g_Wo1T[D * D];                // W_o1^T  [n][k]
__device__ float g_WstkT[D * 384];             // [n][ Wrel0col | Wrel1col | Wrootcol ]
__device__ int   g_src[N_EDGES];
__device__ int   g_dst[N_EDGES];
__device__ int   g_typ[N_EDGES];
__device__ int   g_cnt[NR];
__device__ int   g_fill[NR];
__device__ int   g_rs[NR + 1];
__device__ int   g_bsums[256];
__device__ int   g_flag[2];
__device__ int   g_csr[N_EDGES];

// ----------------------------- dtype detection -----------------------------
__global__ void k_detect(const unsigned int* __restrict__ ei,
                         const unsigned int* __restrict__ et) {
    __shared__ int nz_i, nz_t;
    if (threadIdx.x == 0) { nz_i = 0; nz_t = 0; }
    __syncthreads();
    for (int i = threadIdx.x; i < 512; i += blockDim.x) {
        if (ei[2 * i + 1] != 0u) atomicOr(&nz_i, 1);
        if (et[2 * i + 1] != 0u) atomicOr(&nz_t, 1);
    }
    __syncthreads();
    if (threadIdx.x == 0) {
        g_flag[0] = (nz_i == 0) ? 1 : 0;
        g_flag[1] = (nz_t == 0) ? 1 : 0;
    }
}

// convert + histogram in one pass over the edge list
__global__ void k_convert_hist(const void* __restrict__ ei, const void* __restrict__ et) {
    int i = blockIdx.x * blockDim.x + threadIdx.x;
    if (i >= N_EDGES) return;
    int s, d, t;
    if (g_flag[0]) {
        const long long* p = (const long long*)ei;
        s = (int)p[i]; d = (int)p[(size_t)N_EDGES + i];
    } else {
        const int* p = (const int*)ei;
        s = p[i]; d = p[N_EDGES + i];
    }
    if (g_flag[1]) t = (int)((const long long*)et)[i];
    else           t = ((const int*)et)[i];
    g_src[i] = s; g_dst[i] = d; g_typ[i] = t;
    atomicAdd(&g_cnt[d * R + t], 1);
}

// ----------------------------- CSR build -----------------------------------
__global__ void k_zero_seg() {
    int i = blockIdx.x * blockDim.x + threadIdx.x;
    if (i < NR) { g_cnt[i] = 0; g_fill[i] = 0; }
}

__global__ void k_scan1() {
    __shared__ int sh[256];
    int b = blockIdx.x, t = threadIdx.x;
    int s = 0;
    #pragma unroll
    for (int i = 0; i < 4; i++) {
        int idx = b * SCAN_CHUNK + t * 4 + i;
        if (idx < NR) s += g_cnt[idx];
    }
    sh[t] = s; __syncthreads();
    for (int off = 128; off > 0; off >>= 1) {
        if (t < off) sh[t] += sh[t + off];
        __syncthreads();
    }
    if (t == 0) g_bsums[b] = sh[0];
}

__global__ void k_scan2() {
    __shared__ int sh[256];
    int t = threadIdx.x;
    sh[t] = (t < SCAN_NB) ? g_bsums[t] : 0;
    __syncthreads();
    if (t == 0) {
        int run = 0;
        for (int i = 0; i < SCAN_NB; i++) { int c = sh[i]; sh[i] = run; run += c; }
        g_rs[NR] = N_EDGES;
    }
    __syncthreads();
    if (t < SCAN_NB) g_bsums[t] = sh[t];
}

__global__ void k_scan3() {
    __shared__ int sh[256];
    int b = blockIdx.x, t = threadIdx.x;
    int base = b * SCAN_CHUNK;
    int v[4]; int s = 0;
    #pragma unroll
    for (int i = 0; i < 4; i++) {
        int idx = base + t * 4 + i;
        v[i] = (idx < NR) ? g_cnt[idx] : 0;
        s += v[i];
    }
    sh[t] = s; __syncthreads();
    for (int off = 1; off < 256; off <<= 1) {
        int cur = sh[t];
        int y = (t >= off) ? sh[t - off] : 0;
        __syncthreads();
        sh[t] = cur + y;
        __syncthreads();
    }
    int run = g_bsums[b] + sh[t] - s;
    #pragma unroll
    for (int i = 0; i < 4; i++) {
        int idx = base + t * 4 + i;
        if (idx < NR) g_rs[idx] = run;
        run += v[i];
    }
}

__global__ void k_fill() {
    int i = blockIdx.x * blockDim.x + threadIdx.x;
    if (i >= N_EDGES) return;
    int seg = g_dst[i] * R + g_typ[i];
    int pos = atomicAdd(&g_fill[seg], 1);
    g_csr[g_rs[seg] + pos] = g_src[i];
}

// ----------------------------- feature encoder -----------------------------
__global__ void k_encode(const float* __restrict__ des, const float* __restrict__ twt,
                         const float* __restrict__ nump, const float* __restrict__ catp,
                         const float* __restrict__ Wd, const float* __restrict__ bd,
                         const float* __restrict__ Wt, const float* __restrict__ bt,
                         const float* __restrict__ Wn, const float* __restrict__ bn,
                         const float* __restrict__ Wc, const float* __restrict__ bc) {
    int n = blockIdx.x;
    __shared__ float sin[224];
    int t = threadIdx.x;
    if (t < 100) sin[t] = des[(size_t)n * 100 + t];
    for (int i = t; i < 100; i += 128) sin[100 + i] = twt[(size_t)n * 100 + i];
    if (t < 6)  sin[200 + t] = nump[(size_t)n * 6 + t];
    if (t < 11) sin[206 + t] = catp[(size_t)n * 11 + t];
    __syncthreads();

    int q = t >> 5, j = t & 31;
    const float* W; const float* b; const float* in; int fan;
    if (q == 0)      { W = Wd; b = bd; in = sin;       fan = 100; }
    else if (q == 1) { W = Wt; b = bt; in = sin + 100; fan = 100; }
    else if (q == 2) { W = Wn; b = bn; in = sin + 200; fan = 6;   }
    else             { W = Wc; b = bc; in = sin + 206; fan = 11;  }
    float acc = b[j];
    for (int k = 0; k < fan; k++) acc = fmaf(in[k], W[k * 32 + j], acc);
    acc = acc > 0.f ? acc : 0.01f * acc;
    g_XA[(size_t)n * D + t] = acc;
}

// ----------------------------- transpose pack: dst[n*ldD + off + k] = src[k*N + n]
__global__ void k_packT(const float* __restrict__ src, float* __restrict__ dst,
                        int K, int N, int ldD, int off) {
    int i = blockIdx.x * blockDim.x + threadIdx.x;
    if (i >= K * N) return;
    int k = i / N, n = i % N;
    dst[(size_t)n * ldD + off + k] = src[i];
}

// ----------------------------- single-pass TF32 mma.sync GEMM --------------
// C[M,128] = A[M,kTot] @ Bt[128,kTot]^T + bias (optional lrelu).
// A = A1 rows for k<kSplit else A2 (concat along K). 256 threads, tile 128x128,
// 8 warps as 4(m) x 2(n), each warp 32x64. K-slabs of 32.

#define LDS 36   // padded row stride in 4B words

__device__ __forceinline__ unsigned f2tf(float x) {
    unsigned r; asm("cvt.rna.tf32.f32 %0, %1;" : "=r"(r) : "f"(x)); return r;
}

__device__ __forceinline__ void mma_tf32(float* c, const unsigned* a,
                                         unsigned b0, unsigned b1) {
    asm volatile(
        "mma.sync.aligned.m16n8k8.row.col.f32.tf32.tf32.f32 "
        "{%0,%1,%2,%3}, {%4,%5,%6,%7}, {%8,%9}, {%0,%1,%2,%3};"
        : "+f"(c[0]), "+f"(c[1]), "+f"(c[2]), "+f"(c[3])
        : "r"(a[0]), "r"(a[1]), "r"(a[2]), "r"(a[3]), "r"(b0), "r"(b1));
}

__global__ __launch_bounds__(256) void k_gemm_tc(
    const float* __restrict__ A1, int ldA1,
    const float* __restrict__ A2, int ldA2,
    int kSplit, int kTot,
    const float* __restrict__ Bt,
    float* __restrict__ C, int M,
    const float* __restrict__ bias, int act)
{
    __shared__ unsigned sA[128 * LDS];
    __shared__ unsigned sB[128 * LDS];

    int tid = threadIdx.x;
    int wid = tid >> 5, lane = tid & 31;
    int gid = lane >> 2, tig = lane & 3;
    int warp_m = wid & 3, warp_n = wid >> 2;
    int bm = blockIdx.x * 128;

    int srow = tid >> 1;          // staging row 0..127
    int shalf = tid & 1;          // which 16-wide half of the 32-slab
    int arow = bm + srow; if (arow > M - 1) arow = M - 1;

    float acc[2][8][4];
    #pragma unroll
    for (int i = 0; i < 2; i++)
        #pragma unroll
        for (int j = 0; j < 8; j++)
            #pragma unroll
            for (int q = 0; q < 4; q++) acc[i][j][q] = 0.f;

    int nSlab = kTot >> 5;
    for (int s = 0; s < nSlab; s++) {
        int k0 = s << 5;
        const float* asrc = (k0 < kSplit)
            ? A1 + (size_t)arow * ldA1 + k0 + shalf * 16
            : A2 + (size_t)arow * ldA2 + (k0 - kSplit) + shalf * 16;
        #pragma unroll
        for (int j = 0; j < 4; j++) {
            float4 v = *(const float4*)(asrc + j * 4);
            int o = srow * LDS + shalf * 16 + j * 4;
            *(uint4*)(sA + o) = make_uint4(f2tf(v.x), f2tf(v.y), f2tf(v.z), f2tf(v.w));
        }
        const float* bsrc = Bt + (size_t)srow * kTot + k0 + shalf * 16;
        #pragma unroll
        for (int j = 0; j < 4; j++) {
            float4 v = *(const float4*)(bsrc + j * 4);
            int o = srow * LDS + shalf * 16 + j * 4;
            *(uint4*)(sB + o) = make_uint4(f2tf(v.x), f2tf(v.y), f2tf(v.z), f2tf(v.w));
        }
        __syncthreads();

        #pragma unroll
        for (int kk = 0; kk < 4; kk++) {
            int kk8 = kk << 3;
            unsigned ah[2][4];
            #pragma unroll
            for (int mf = 0; mf < 2; mf++) {
                int r0 = (warp_m * 32 + mf * 16 + gid) * LDS + kk8 + tig;
                int r1 = r0 + 8 * LDS;
                ah[mf][0] = sA[r0]; ah[mf][1] = sA[r1];
                ah[mf][2] = sA[r0 + 4]; ah[mf][3] = sA[r1 + 4];
            }
            #pragma unroll
            for (int nf = 0; nf < 8; nf++) {
                int nb = (warp_n * 64 + nf * 8 + gid) * LDS + kk8 + tig;
                unsigned b0 = sB[nb], b1 = sB[nb + 4];
                #pragma unroll
                for (int mf = 0; mf < 2; mf++)
                    mma_tf32(acc[mf][nf], ah[mf], b0, b1);
            }
        }
        __syncthreads();
    }

    // ---- epilogue ----
    #pragma unroll
    for (int mf = 0; mf < 2; mf++) {
        int r0 = bm + warp_m * 32 + mf * 16 + gid;
        int r1 = r0 + 8;
        #pragma unroll
        for (int nf = 0; nf < 8; nf++) {
            int c = warp_n * 64 + nf * 8 + tig * 2;
            float b0 = bias[c], b1 = bias[c + 1];
            float v0 = acc[mf][nf][0] + b0, v1 = acc[mf][nf][1] + b1;
            float v2 = acc[mf][nf][2] + b0, v3 = acc[mf][nf][3] + b1;
            if (act) {
                v0 = v0 > 0.f ? v0 : 0.01f * v0;
                v1 = v1 > 0.f ? v1 : 0.01f * v1;
                v2 = v2 > 0.f ? v2 : 0.01f * v2;
                v3 = v3 > 0.f ? v3 : 0.01f * v3;
            }
            if (r0 < M) *(float2*)(C + (size_t)r0 * 128 + c) = make_float2(v0, v1);
            if (r1 < M) *(float2*)(C + (size_t)r1 * 128 + c) = make_float2(v2, v3);
        }
    }
}

// ----------------------------- aggregation (mean per (node,rel) from X) ----
__global__ void k_agg2(const float* __restrict__ X, float* __restrict__ Mout) {
    int w = (blockIdx.x * blockDim.x + threadIdx.x) >> 5;
    if (w >= NR) return;
    int lane = threadIdx.x & 31;
    int n = w >> 1, rel = w & 1;
    int s = g_rs[w], e = g_rs[w + 1];
    float4 sum = make_float4(0.f, 0.f, 0.f, 0.f);
    int i = s;
    for (; i + 4 <= e; i += 4) {
        int i0 = g_csr[i], i1 = g_csr[i + 1], i2 = g_csr[i + 2], i3 = g_csr[i + 3];
        float4 a = ((const float4*)(X + (size_t)i0 * D))[lane];
        float4 b = ((const float4*)(X + (size_t)i1 * D))[lane];
        float4 c = ((const float4*)(X + (size_t)i2 * D))[lane];
        float4 d = ((const float4*)(X + (size_t)i3 * D))[lane];
        sum.x += a.x + b.x + c.x + d.x;
        sum.y += a.y + b.y + c.y + d.y;
        sum.z += a.z + b.z + c.z + d.z;
        sum.w += a.w + b.w + c.w + d.w;
    }
    for (; i < e; i++) {
        float4 a = ((const float4*)(X + (size_t)g_csr[i] * D))[lane];
        sum.x += a.x; sum.y += a.y; sum.z += a.z; sum.w += a.w;
    }
    float inv = (e > s) ? 1.0f / (float)(e - s) : 0.0f;
    sum.x *= inv; sum.y *= inv; sum.z *= inv; sum.w *= inv;
    ((float4*)(Mout + (size_t)n * 256 + rel * D))[lane] = sum;
}

// ----------------------------- final projection to 2 classes ---------------
__global__ void k_final(const float* __restrict__ Y, const float* __restrict__ Wo2,
                        const float* __restrict__ bo2, float* __restrict__ out) {
    int warp = (blockIdx.x * blockDim.x + threadIdx.x) >> 5;
    int lane = threadIdx.x & 31;
    if (warp >= N_NODES) return;
    float4 y = ((const float4*)(Y + (size_t)warp * D))[lane];
    int k0 = lane * 4;
    float s0 = y.x * Wo2[(k0 + 0) * 2 + 0] + y.y * Wo2[(k0 + 1) * 2 + 0]
             + y.z * Wo2[(k0 + 2) * 2 + 0] + y.w * Wo2[(k0 + 3) * 2 + 0];
    float s1 = y.x * Wo2[(k0 + 0) * 2 + 1] + y.y * Wo2[(k0 + 1) * 2 + 1]
             + y.z * Wo2[(k0 + 2) * 2 + 1] + y.w * Wo2[(k0 + 3) * 2 + 1];
    #pragma unroll
    for (int off = 16; off > 0; off >>= 1) {
        s0 += __shfl_down_sync(0xFFFFFFFFu, s0, off);
        s1 += __shfl_down_sync(0xFFFFFFFFu, s1, off);
    }
    if (lane == 0) {
        out[(size_t)warp * 2 + 0] = s0 + bo2[0];
        out[(size_t)warp * 2 + 1] = s1 + bo2[1];
    }
}

// ----------------------------- launch --------------------------------------
extern "C" void kernel_launch(void* const* d_in, const int* in_sizes, int n_in,
                              void* d_out, int out_size) {
    const float* des   = (const float*)d_in[0];
    const float* twt   = (const float*)d_in[1];
    const float* nump  = (const float*)d_in[2];
    const float* catp  = (const float*)d_in[3];
    const void*  ei    = d_in[4];
    const void*  et    = d_in[5];
    const float* Wd    = (const float*)d_in[6];
    const float* bd    = (const float*)d_in[7];
    const float* Wt    = (const float*)d_in[8];
    const float* bt    = (const float*)d_in[9];
    const float* Wn    = (const float*)d_in[10];
    const float* bn    = (const float*)d_in[11];
    const float* Wc    = (const float*)d_in[12];
    const float* bc    = (const float*)d_in[13];
    const float* W_in  = (const float*)d_in[14];
    const float* b_in  = (const float*)d_in[15];
    const float* W_rel = (const float*)d_in[16];
    const float* W_root= (const float*)d_in[17];
    const float* b_rg  = (const float*)d_in[18];
    const float* W_o1  = (const float*)d_in[19];
    const float* b_o1  = (const float*)d_in[20];
    const float* W_o2  = (const float*)d_in[21];
    const float* b_o2  = (const float*)d_in[22];
    float* out = (float*)d_out;

    float *XA, *XB, *Mg, *WinT, *Wo1T, *WstkT;
    cudaGetSymbolAddress((void**)&XA, g_XA);
    cudaGetSymbolAddress((void**)&XB, g_XB);
    cudaGetSymbolAddress((void**)&Mg, g_M);
    cudaGetSymbolAddress((void**)&WinT, g_WinT);
    cudaGetSymbolAddress((void**)&Wo1T, g_Wo1T);
    cudaGetSymbolAddress((void**)&WstkT, g_WstkT);

    const int TB = 256;
    int ceb = (N_EDGES + TB - 1) / TB;

    // --- edge preprocessing / CSR build ---
    k_detect<<<1, 64>>>((const unsigned int*)ei, (const unsigned int*)et);
    k_zero_seg<<<(NR + TB - 1) / TB, TB>>>();
    k_convert_hist<<<ceb, TB>>>(ei, et);
    k_scan1<<<SCAN_NB, 256>>>();
    k_scan2<<<1, 256>>>();
    k_scan3<<<SCAN_NB, 256>>>();
    k_fill<<<ceb, TB>>>();

    // --- feature encoding + weight packing ---
    k_encode<<<N_NODES, 128>>>(des, twt, nump, catp, Wd, bd, Wt, bt, Wn, bn, Wc, bc);
    k_packT<<<64, 256>>>(W_in,           WinT,  128, 128, 128, 0);
    k_packT<<<64, 256>>>(W_o1,           Wo1T,  128, 128, 128, 0);
    k_packT<<<64, 256>>>(W_rel,          WstkT, 128, 128, 384, 0);
    k_packT<<<64, 256>>>(W_rel + 16384,  WstkT, 128, 128, 384, 128);
    k_packT<<<64, 256>>>(W_root,         WstkT, 128, 128, 384, 256);

    int gGemm = (N_NODES + 127) / 128;      // 782
    int gAgg  = (NR * 32 + TB - 1) / TB;    // 25000

    // x1 = lrelu(x0 @ W_in + b_in)
    k_gemm_tc<<<gGemm, 256>>>(XA, 128, XA, 128, 128, 128, WinT, XB, N_NODES, b_in, 1);

    // RGCN layer 1: M = means(XB); XA = [M|XB] @ WstkT^T + b_rg
    k_agg2<<<gAgg, TB>>>(XB, Mg);
    k_gemm_tc<<<gGemm, 256>>>(Mg, 256, XB, 128, 256, 384, WstkT, XA, N_NODES, b_rg, 0);

    // RGCN layer 2: M = means(XA); XB = [M|XA] @ WstkT^T + b_rg
    k_agg2<<<gAgg, TB>>>(XA, Mg);
    k_gemm_tc<<<gGemm, 256>>>(Mg, 256, XA, 128, 256, 384, WstkT, XB, N_NODES, b_rg, 0);

    // x4 = lrelu(x3 @ W_o1 + b_o1); out = x4 @ W_o2 + b_o2
    k_gemm_tc<<<gGemm, 256>>>(XB, 128, XB, 128, 128, 128, Wo1T, XA, N_NODES, b_o1, 1);
    k_final<<<(N_NODES * 32 + TB - 1) / TB, TB>>>(XA, W_o2, b_o2, out);
}

// round 7
// speedup vs baseline: 1.9226x; 1.0836x over previous
#include <cuda_runtime.h>
#include <cstdint>

#define N_NODES 100000
#define N_EDGES 1600000
#define D 128
#define R 2
#define NR (N_NODES * R)          // 200000 segments
#define SCAN_CHUNK 1024
#define SCAN_NB ((NR + SCAN_CHUNK - 1) / SCAN_CHUNK)   // 196

// ----------------------------- scratch (static device globals; no allocs) ---
__device__ float g_XA[(size_t)N_NODES * D];
__device__ float g_XB[(size_t)N_NODES * D];
__device__ float g_M[(size_t)N_NODES * 256];   // [mean_rel0 | mean_rel1]
__device__ float g_WinT[D * D];                // W_in^T  [n][k]
__device__ float g_Wo1T[D * D];                // W_o1^T  [n][k]
__device__ float g_WstkT[D * 384];             // [n][ Wrel0col | Wrel1col | Wrootcol ]
__device__ int   g_src[N_EDGES];
__device__ int   g_dst[N_EDGES];
__device__ int   g_typ[N_EDGES];
__device__ int   g_cnt[NR];
__device__ int   g_fill[NR];
__device__ int   g_rs[NR + 1];
__device__ int   g_bsums[256];
__device__ int   g_flag[2];
__device__ int   g_csr[N_EDGES];

// ----------------------------- dtype detection -----------------------------
__global__ void k_detect(const unsigned int* __restrict__ ei,
                         const unsigned int* __restrict__ et) {
    __shared__ int nz_i, nz_t;
    if (threadIdx.x == 0) { nz_i = 0; nz_t = 0; }
    __syncthreads();
    for (int i = threadIdx.x; i < 512; i += blockDim.x) {
        if (ei[2 * i + 1] != 0u) atomicOr(&nz_i, 1);
        if (et[2 * i + 1] != 0u) atomicOr(&nz_t, 1);
    }
    __syncthreads();
    if (threadIdx.x == 0) {
        g_flag[0] = (nz_i == 0) ? 1 : 0;
        g_flag[1] = (nz_t == 0) ? 1 : 0;
    }
}

// convert + histogram in one pass over the edge list
__global__ void k_convert_hist(const void* __restrict__ ei, const void* __restrict__ et) {
    int i = blockIdx.x * blockDim.x + threadIdx.x;
    if (i >= N_EDGES) return;
    int s, d, t;
    if (g_flag[0]) {
        const long long* p = (const long long*)ei;
        s = (int)p[i]; d = (int)p[(size_t)N_EDGES + i];
    } else {
        const int* p = (const int*)ei;
        s = p[i]; d = p[N_EDGES + i];
    }
    if (g_flag[1]) t = (int)((const long long*)et)[i];
    else           t = ((const int*)et)[i];
    g_src[i] = s; g_dst[i] = d; g_typ[i] = t;
    atomicAdd(&g_cnt[d * R + t], 1);
}

// ----------------------------- CSR build -----------------------------------
__global__ void k_zero_seg() {
    int i = blockIdx.x * blockDim.x + threadIdx.x;
    if (i < NR) { g_cnt[i] = 0; g_fill[i] = 0; }
}

__global__ void k_scan1() {
    __shared__ int sh[256];
    int b = blockIdx.x, t = threadIdx.x;
    int s = 0;
    #pragma unroll
    for (int i = 0; i < 4; i++) {
        int idx = b * SCAN_CHUNK + t * 4 + i;
        if (idx < NR) s += g_cnt[idx];
    }
    sh[t] = s; __syncthreads();
    for (int off = 128; off > 0; off >>= 1) {
        if (t < off) sh[t] += sh[t + off];
        __syncthreads();
    }
    if (t == 0) g_bsums[b] = sh[0];
}

__global__ void k_scan2() {
    __shared__ int sh[256];
    int t = threadIdx.x;
    sh[t] = (t < SCAN_NB) ? g_bsums[t] : 0;
    __syncthreads();
    if (t == 0) {
        int run = 0;
        for (int i = 0; i < SCAN_NB; i++) { int c = sh[i]; sh[i] = run; run += c; }
        g_rs[NR] = N_EDGES;
    }
    __syncthreads();
    if (t < SCAN_NB) g_bsums[t] = sh[t];
}

__global__ void k_scan3() {
    __shared__ int sh[256];
    int b = blockIdx.x, t = threadIdx.x;
    int base = b * SCAN_CHUNK;
    int v[4]; int s = 0;
    #pragma unroll
    for (int i = 0; i < 4; i++) {
        int idx = base + t * 4 + i;
        v[i] = (idx < NR) ? g_cnt[idx] : 0;
        s += v[i];
    }
    sh[t] = s; __syncthreads();
    for (int off = 1; off < 256; off <<= 1) {
        int cur = sh[t];
        int y = (t >= off) ? sh[t - off] : 0;
        __syncthreads();
        sh[t] = cur + y;
        __syncthreads();
    }
    int run = g_bsums[b] + sh[t] - s;
    #pragma unroll
    for (int i = 0; i < 4; i++) {
        int idx = base + t * 4 + i;
        if (idx < NR) g_rs[idx] = run;
        run += v[i];
    }
}

__global__ void k_fill() {
    int i = blockIdx.x * blockDim.x + threadIdx.x;
    if (i >= N_EDGES) return;
    int seg = g_dst[i] * R + g_typ[i];
    int pos = atomicAdd(&g_fill[seg], 1);
    g_csr[g_rs[seg] + pos] = g_src[i];
}

// ----------------------------- feature encoder -----------------------------
__global__ void k_encode(const float* __restrict__ des, const float* __restrict__ twt,
                         const float* __restrict__ nump, const float* __restrict__ catp,
                         const float* __restrict__ Wd, const float* __restrict__ bd,
                         const float* __restrict__ Wt, const float* __restrict__ bt,
                         const float* __restrict__ Wn, const float* __restrict__ bn,
                         const float* __restrict__ Wc, const float* __restrict__ bc) {
    int n = blockIdx.x;
    __shared__ float sin[224];
    int t = threadIdx.x;
    if (t < 100) sin[t] = des[(size_t)n * 100 + t];
    for (int i = t; i < 100; i += 128) sin[100 + i] = twt[(size_t)n * 100 + i];
    if (t < 6)  sin[200 + t] = nump[(size_t)n * 6 + t];
    if (t < 11) sin[206 + t] = catp[(size_t)n * 11 + t];
    __syncthreads();

    int q = t >> 5, j = t & 31;
    const float* W; const float* b; const float* in; int fan;
    if (q == 0)      { W = Wd; b = bd; in = sin;       fan = 100; }
    else if (q == 1) { W = Wt; b = bt; in = sin + 100; fan = 100; }
    else if (q == 2) { W = Wn; b = bn; in = sin + 200; fan = 6;   }
    else             { W = Wc; b = bc; in = sin + 206; fan = 11;  }
    float acc = b[j];
    for (int k = 0; k < fan; k++) acc = fmaf(in[k], W[k * 32 + j], acc);
    acc = acc > 0.f ? acc : 0.01f * acc;
    g_XA[(size_t)n * D + t] = acc;
}

// ----------------------------- weight pack (all transposes in one kernel) --
// regions of 16384 elements each: 0:WinT 1:Wo1T 2:Wstk(rel0) 3:Wstk(rel1) 4:Wstk(root)
__global__ void k_packAll(const float* __restrict__ W_in, const float* __restrict__ W_o1,
                          const float* __restrict__ W_rel, const float* __restrict__ W_root) {
    int i = blockIdx.x * blockDim.x + threadIdx.x;
    if (i >= 5 * 16384) return;
    int reg = i >> 14, r = i & 16383;
    int k = r >> 7, n = r & 127;
    if (reg == 0)      g_WinT[n * 128 + k] = W_in[r];
    else if (reg == 1) g_Wo1T[n * 128 + k] = W_o1[r];
    else if (reg == 2) g_WstkT[n * 384 + k]       = W_rel[r];
    else if (reg == 3) g_WstkT[n * 384 + 128 + k] = W_rel[16384 + r];
    else               g_WstkT[n * 384 + 256 + k] = W_root[r];
}

// ----------------------------- single-pass TF32 mma.sync GEMM --------------
// C[M,128] = A[M,kTot] @ Bt[128,kTot]^T + bias (optional lrelu).
// If out2 != nullptr: instead of storing C, project to 2 classes:
//   out2[r] = lrelu(C_row) @ Wo2 + bo2   (fused final layer)
// A = A1 rows for k<kSplit else A2 (concat along K). 256 threads, tile 128x128,
// 8 warps as 4(m) x 2(n), each warp 32x64. K-slabs of 32.

#define LDS 36   // padded row stride in 4B words

__device__ __forceinline__ unsigned f2tf(float x) {
    unsigned r; asm("cvt.rna.tf32.f32 %0, %1;" : "=r"(r) : "f"(x)); return r;
}

__device__ __forceinline__ void mma_tf32(float* c, const unsigned* a,
                                         unsigned b0, unsigned b1) {
    asm volatile(
        "mma.sync.aligned.m16n8k8.row.col.f32.tf32.tf32.f32 "
        "{%0,%1,%2,%3}, {%4,%5,%6,%7}, {%8,%9}, {%0,%1,%2,%3};"
        : "+f"(c[0]), "+f"(c[1]), "+f"(c[2]), "+f"(c[3])
        : "r"(a[0]), "r"(a[1]), "r"(a[2]), "r"(a[3]), "r"(b0), "r"(b1));
}

__global__ __launch_bounds__(256) void k_gemm_tc(
    const float* __restrict__ A1, int ldA1,
    const float* __restrict__ A2, int ldA2,
    int kSplit, int kTot,
    const float* __restrict__ Bt,
    float* __restrict__ C, int M,
    const float* __restrict__ bias, int act,
    const float* __restrict__ Wo2, const float* __restrict__ bo2,
    float* __restrict__ out2)
{
    __shared__ unsigned sA[128 * LDS];
    __shared__ unsigned sB[128 * LDS];

    int tid = threadIdx.x;
    int wid = tid >> 5, lane = tid & 31;
    int gid = lane >> 2, tig = lane & 3;
    int warp_m = wid & 3, warp_n = wid >> 2;
    int bm = blockIdx.x * 128;

    int srow = tid >> 1;          // staging row 0..127
    int shalf = tid & 1;          // which 16-wide half of the 32-slab
    int arow = bm + srow; if (arow > M - 1) arow = M - 1;

    float acc[2][8][4];
    #pragma unroll
    for (int i = 0; i < 2; i++)
        #pragma unroll
        for (int j = 0; j < 8; j++)
            #pragma unroll
            for (int q = 0; q < 4; q++) acc[i][j][q] = 0.f;

    int nSlab = kTot >> 5;
    for (int s = 0; s < nSlab; s++) {
        int k0 = s << 5;
        const float* asrc = (k0 < kSplit)
            ? A1 + (size_t)arow * ldA1 + k0 + shalf * 16
            : A2 + (size_t)arow * ldA2 + (k0 - kSplit) + shalf * 16;
        #pragma unroll
        for (int j = 0; j < 4; j++) {
            float4 v = *(const float4*)(asrc + j * 4);
            int o = srow * LDS + shalf * 16 + j * 4;
            *(uint4*)(sA + o) = make_uint4(f2tf(v.x), f2tf(v.y), f2tf(v.z), f2tf(v.w));
        }
        const float* bsrc = Bt + (size_t)srow * kTot + k0 + shalf * 16;
        #pragma unroll
        for (int j = 0; j < 4; j++) {
            float4 v = *(const float4*)(bsrc + j * 4);
            int o = srow * LDS + shalf * 16 + j * 4;
            *(uint4*)(sB + o) = make_uint4(f2tf(v.x), f2tf(v.y), f2tf(v.z), f2tf(v.w));
        }
        __syncthreads();

        #pragma unroll
        for (int kk = 0; kk < 4; kk++) {
            int kk8 = kk << 3;
            unsigned ah[2][4];
            #pragma unroll
            for (int mf = 0; mf < 2; mf++) {
                int r0 = (warp_m * 32 + mf * 16 + gid) * LDS + kk8 + tig;
                int r1 = r0 + 8 * LDS;
                ah[mf][0] = sA[r0]; ah[mf][1] = sA[r1];
                ah[mf][2] = sA[r0 + 4]; ah[mf][3] = sA[r1 + 4];
            }
            #pragma unroll
            for (int nf = 0; nf < 8; nf++) {
                int nb = (warp_n * 64 + nf * 8 + gid) * LDS + kk8 + tig;
                unsigned b0 = sB[nb], b1 = sB[nb + 4];
                #pragma unroll
                for (int mf = 0; mf < 2; mf++)
                    mma_tf32(acc[mf][nf], ah[mf], b0, b1);
            }
        }
        __syncthreads();
    }

    if (out2 == nullptr) {
        // ---- standard epilogue: bias (+lrelu) and store C ----
        #pragma unroll
        for (int mf = 0; mf < 2; mf++) {
            int r0 = bm + warp_m * 32 + mf * 16 + gid;
            int r1 = r0 + 8;
            #pragma unroll
            for (int nf = 0; nf < 8; nf++) {
                int c = warp_n * 64 + nf * 8 + tig * 2;
                float b0 = bias[c], b1 = bias[c + 1];
                float v0 = acc[mf][nf][0] + b0, v1 = acc[mf][nf][1] + b1;
                float v2 = acc[mf][nf][2] + b0, v3 = acc[mf][nf][3] + b1;
                if (act) {
                    v0 = v0 > 0.f ? v0 : 0.01f * v0;
                    v1 = v1 > 0.f ? v1 : 0.01f * v1;
                    v2 = v2 > 0.f ? v2 : 0.01f * v2;
                    v3 = v3 > 0.f ? v3 : 0.01f * v3;
                }
                if (r0 < M) *(float2*)(C + (size_t)r0 * 128 + c) = make_float2(v0, v1);
                if (r1 < M) *(float2*)(C + (size_t)r1 * 128 + c) = make_float2(v2, v3);
            }
        }
    } else {
        // ---- fused final projection: out2[r] = lrelu(C_row+bias) @ Wo2 + bo2 ----
        float p[2][2][2] = {{{0.f,0.f},{0.f,0.f}},{{0.f,0.f},{0.f,0.f}}};
        #pragma unroll
        for (int mf = 0; mf < 2; mf++) {
            #pragma unroll
            for (int nf = 0; nf < 8; nf++) {
                int c = warp_n * 64 + nf * 8 + tig * 2;
                float b0 = bias[c], b1 = bias[c + 1];
                float v0 = acc[mf][nf][0] + b0, v1 = acc[mf][nf][1] + b1;
                float v2 = acc[mf][nf][2] + b0, v3 = acc[mf][nf][3] + b1;
                if (act) {
                    v0 = v0 > 0.f ? v0 : 0.01f * v0;
                    v1 = v1 > 0.f ? v1 : 0.01f * v1;
                    v2 = v2 > 0.f ? v2 : 0.01f * v2;
                    v3 = v3 > 0.f ? v3 : 0.01f * v3;
                }
                float w00 = Wo2[c * 2 + 0], w01 = Wo2[c * 2 + 1];
                float w10 = Wo2[c * 2 + 2], w11 = Wo2[c * 2 + 3];
                p[mf][0][0] = fmaf(v0, w00, fmaf(v1, w10, p[mf][0][0]));
                p[mf][0][1] = fmaf(v0, w01, fmaf(v1, w11, p[mf][0][1]));
                p[mf][1][0] = fmaf(v2, w00, fmaf(v3, w10, p[mf][1][0]));
                p[mf][1][1] = fmaf(v2, w01, fmaf(v3, w11, p[mf][1][1]));
            }
        }
        // reduce over tig (lanes gid*4+tig, xor 1 and 2 stay in the group)
        #pragma unroll
        for (int m = 1; m < 4; m <<= 1) {
            #pragma unroll
            for (int mf = 0; mf < 2; mf++)
                #pragma unroll
                for (int h = 0; h < 2; h++)
                    #pragma unroll
                    for (int j = 0; j < 2; j++)
                        p[mf][h][j] += __shfl_xor_sync(0xFFFFFFFFu, p[mf][h][j], m);
        }
        __syncthreads();
        float* sRed = (float*)sA;   // 256 floats used
        if (warp_n == 0 && tig == 0) {
            #pragma unroll
            for (int mf = 0; mf < 2; mf++)
                #pragma unroll
                for (int h = 0; h < 2; h++) {
                    int rid = warp_m * 32 + mf * 16 + h * 8 + gid;
                    sRed[rid * 2 + 0] = p[mf][h][0];
                    sRed[rid * 2 + 1] = p[mf][h][1];
                }
        }
        __syncthreads();
        if (warp_n == 1 && tig == 0) {
            #pragma unroll
            for (int mf = 0; mf < 2; mf++)
                #pragma unroll
                for (int h = 0; h < 2; h++) {
                    int rid = warp_m * 32 + mf * 16 + h * 8 + gid;
                    int row = bm + rid;
                    if (row < M) {
                        out2[(size_t)row * 2 + 0] = p[mf][h][0] + sRed[rid * 2 + 0] + bo2[0];
                        out2[(size_t)row * 2 + 1] = p[mf][h][1] + sRed[rid * 2 + 1] + bo2[1];
                    }
                }
        }
    }
}

// ----------------------------- aggregation (mean per (node,rel) from X) ----
__global__ void k_agg2(const float* __restrict__ X, float* __restrict__ Mout) {
    int w = (blockIdx.x * blockDim.x + threadIdx.x) >> 5;
    if (w >= NR) return;
    int lane = threadIdx.x & 31;
    int n = w >> 1, rel = w & 1;
    int s = g_rs[w], e = g_rs[w + 1];
    float4 sum = make_float4(0.f, 0.f, 0.f, 0.f);
    int i = s;
    for (; i + 4 <= e; i += 4) {
        int i0 = g_csr[i], i1 = g_csr[i + 1], i2 = g_csr[i + 2], i3 = g_csr[i + 3];
        float4 a = ((const float4*)(X + (size_t)i0 * D))[lane];
        float4 b = ((const float4*)(X + (size_t)i1 * D))[lane];
        float4 c = ((const float4*)(X + (size_t)i2 * D))[lane];
        float4 d = ((const float4*)(X + (size_t)i3 * D))[lane];
        sum.x += a.x + b.x + c.x + d.x;
        sum.y += a.y + b.y + c.y + d.y;
        sum.z += a.z + b.z + c.z + d.z;
        sum.w += a.w + b.w + c.w + d.w;
    }
    for (; i < e; i++) {
        float4 a = ((const float4*)(X + (size_t)g_csr[i] * D))[lane];
        sum.x += a.x; sum.y += a.y; sum.z += a.z; sum.w += a.w;
    }
    float inv = (e > s) ? 1.0f / (float)(e - s) : 0.0f;
    sum.x *= inv; sum.y *= inv; sum.z *= inv; sum.w *= inv;
    ((float4*)(Mout + (size_t)n * 256 + rel * D))[lane] = sum;
}

// ----------------------------- launch --------------------------------------
extern "C" void kernel_launch(void* const* d_in, const int* in_sizes, int n_in,
                              void* d_out, int out_size) {
    const float* des   = (const float*)d_in[0];
    const float* twt   = (const float*)d_in[1];
    const float* nump  = (const float*)d_in[2];
    const float* catp  = (const float*)d_in[3];
    const void*  ei    = d_in[4];
    const void*  et    = d_in[5];
    const float* Wd    = (const float*)d_in[6];
    const float* bd    = (const float*)d_in[7];
    const float* Wt    = (const float*)d_in[8];
    const float* bt    = (const float*)d_in[9];
    const float* Wn    = (const float*)d_in[10];
    const float* bn    = (const float*)d_in[11];
    const float* Wc    = (const float*)d_in[12];
    const float* bc    = (const float*)d_in[13];
    const float* W_in  = (const float*)d_in[14];
    const float* b_in  = (const float*)d_in[15];
    const float* W_rel = (const float*)d_in[16];
    const float* W_root= (const float*)d_in[17];
    const float* b_rg  = (const float*)d_in[18];
    const float* W_o1  = (const float*)d_in[19];
    const float* b_o1  = (const float*)d_in[20];
    const float* W_o2  = (const float*)d_in[21];
    const float* b_o2  = (const float*)d_in[22];
    float* out = (float*)d_out;

    float *XA, *XB, *Mg, *WinT, *Wo1T, *WstkT;
    cudaGetSymbolAddress((void**)&XA, g_XA);
    cudaGetSymbolAddress((void**)&XB, g_XB);
    cudaGetSymbolAddress((void**)&Mg, g_M);
    cudaGetSymbolAddress((void**)&WinT, g_WinT);
    cudaGetSymbolAddress((void**)&Wo1T, g_Wo1T);
    cudaGetSymbolAddress((void**)&WstkT, g_WstkT);

    const int TB = 256;
    int ceb = (N_EDGES + TB - 1) / TB;
    int gGemm = (N_NODES + 127) / 128;      // 782
    int gAgg  = (NR * 32 + TB - 1) / TB;    // 25000

    // side stream for the independent CSR-build chain (leaked; few calls total)
    cudaStream_t s2;
    cudaEvent_t evRoot, evB;
    cudaStreamCreateWithFlags(&s2, cudaStreamNonBlocking);
    cudaEventCreateWithFlags(&evRoot, cudaEventDisableTiming);
    cudaEventCreateWithFlags(&evB, cudaEventDisableTiming);

    cudaEventRecord(evRoot, 0);
    cudaStreamWaitEvent(s2, evRoot, 0);

    // --- main stream: encode -> pack -> GEMM1 ---
    k_encode<<<N_NODES, 128>>>(des, twt, nump, catp, Wd, bd, Wt, bt, Wn, bn, Wc, bc);
    k_packAll<<<(5 * 16384 + TB - 1) / TB, TB>>>(W_in, W_o1, W_rel, W_root);
    k_gemm_tc<<<gGemm, 256>>>(XA, 128, XA, 128, 128, 128, WinT, XB, N_NODES, b_in, 1,
                              nullptr, nullptr, nullptr);

    // --- side stream: CSR build (overlaps the above) ---
    k_zero_seg<<<(NR + TB - 1) / TB, TB, 0, s2>>>();
    k_detect<<<1, 64, 0, s2>>>((const unsigned int*)ei, (const unsigned int*)et);
    k_convert_hist<<<ceb, TB, 0, s2>>>(ei, et);
    k_scan1<<<SCAN_NB, 256, 0, s2>>>();
    k_scan2<<<1, 256, 0, s2>>>();
    k_scan3<<<SCAN_NB, 256, 0, s2>>>();
    k_fill<<<ceb, TB, 0, s2>>>();
    cudaEventRecord(evB, s2);
    cudaStreamWaitEvent(0, evB, 0);

    // RGCN layer 1: M = means(XB); XA = [M|XB] @ WstkT^T + b_rg
    k_agg2<<<gAgg, TB>>>(XB, Mg);
    k_gemm_tc<<<gGemm, 256>>>(Mg, 256, XB, 128, 256, 384, WstkT, XA, N_NODES, b_rg, 0,
                              nullptr, nullptr, nullptr);

    // RGCN layer 2: M = means(XA); XB = [M|XA] @ WstkT^T + b_rg
    k_agg2<<<gAgg, TB>>>(XA, Mg);
    k_gemm_tc<<<gGemm, 256>>>(Mg, 256, XA, 128, 256, 384, WstkT, XB, N_NODES, b_rg, 0,
                              nullptr, nullptr, nullptr);

    // fused: out = lrelu(XB @ Wo1 + b_o1) @ W_o2 + b_o2
    k_gemm_tc<<<gGemm, 256>>>(XB, 128, XB, 128, 128, 128, Wo1T, XA, N_NODES, b_o1, 1,
                              W_o2, b_o2, out);
}

// round 8
// speedup vs baseline: 2.1585x; 1.1227x over previous
#include <cuda_runtime.h>
#include <cuda_fp16.h>
#include <cstdint>

#define N_NODES 100000
#define N_EDGES 1600000
#define D 128
#define R 2
#define NR (N_NODES * R)          // 200000 segments
#define SCAN_CHUNK 1024
#define SCAN_NB ((NR + SCAN_CHUNK - 1) / SCAN_CHUNK)   // 196

// ----------------------------- scratch (static device globals; no allocs) ---
__device__ float g_XA[(size_t)N_NODES * D];
__device__ float g_XB[(size_t)N_NODES * D];
__device__ float g_M[(size_t)N_NODES * 256];   // [mean_rel0 | mean_rel1]
__device__ float g_WinT[D * D];                // W_in^T  [n][k]
__device__ float g_Wo1T[D * D];                // W_o1^T  [n][k]
__device__ float g_WstkT[D * 384];             // [n][ Wrel0col | Wrel1col | Wrootcol ]
__device__ int   g_src[N_EDGES];
__device__ int   g_dst[N_EDGES];
__device__ int   g_typ[N_EDGES];
__device__ int   g_cnt[NR];
__device__ int   g_fill[NR];
__device__ int   g_rs[NR + 1];
__device__ int   g_bsums[256];
__device__ int   g_flag[2];
__device__ int   g_csr[N_EDGES];

// ----------------------------- dtype detection -----------------------------
__global__ void k_detect(const unsigned int* __restrict__ ei,
                         const unsigned int* __restrict__ et) {
    __shared__ int nz_i, nz_t;
    if (threadIdx.x == 0) { nz_i = 0; nz_t = 0; }
    __syncthreads();
    for (int i = threadIdx.x; i < 512; i += blockDim.x) {
        if (ei[2 * i + 1] != 0u) atomicOr(&nz_i, 1);
        if (et[2 * i + 1] != 0u) atomicOr(&nz_t, 1);
    }
    __syncthreads();
    if (threadIdx.x == 0) {
        g_flag[0] = (nz_i == 0) ? 1 : 0;
        g_flag[1] = (nz_t == 0) ? 1 : 0;
    }
}

// convert + histogram in one pass over the edge list
__global__ void k_convert_hist(const void* __restrict__ ei, const void* __restrict__ et) {
    int i = blockIdx.x * blockDim.x + threadIdx.x;
    if (i >= N_EDGES) return;
    int s, d, t;
    if (g_flag[0]) {
        const long long* p = (const long long*)ei;
        s = (int)p[i]; d = (int)p[(size_t)N_EDGES + i];
    } else {
        const int* p = (const int*)ei;
        s = p[i]; d = p[N_EDGES + i];
    }
    if (g_flag[1]) t = (int)((const long long*)et)[i];
    else           t = ((const int*)et)[i];
    g_src[i] = s; g_dst[i] = d; g_typ[i] = t;
    atomicAdd(&g_cnt[d * R + t], 1);
}

// ----------------------------- CSR build -----------------------------------
__global__ void k_zero_seg() {
    int i = blockIdx.x * blockDim.x + threadIdx.x;
    if (i < NR) { g_cnt[i] = 0; g_fill[i] = 0; }
}

__global__ void k_scan1() {
    __shared__ int sh[256];
    int b = blockIdx.x, t = threadIdx.x;
    int s = 0;
    #pragma unroll
    for (int i = 0; i < 4; i++) {
        int idx = b * SCAN_CHUNK + t * 4 + i;
        if (idx < NR) s += g_cnt[idx];
    }
    sh[t] = s; __syncthreads();
    for (int off = 128; off > 0; off >>= 1) {
        if (t < off) sh[t] += sh[t + off];
        __syncthreads();
    }
    if (t == 0) g_bsums[b] = sh[0];
}

__global__ void k_scan2() {
    __shared__ int sh[256];
    int t = threadIdx.x;
    sh[t] = (t < SCAN_NB) ? g_bsums[t] : 0;
    __syncthreads();
    if (t == 0) {
        int run = 0;
        for (int i = 0; i < SCAN_NB; i++) { int c = sh[i]; sh[i] = run; run += c; }
        g_rs[NR] = N_EDGES;
    }
    __syncthreads();
    if (t < SCAN_NB) g_bsums[t] = sh[t];
}

__global__ void k_scan3() {
    __shared__ int sh[256];
    int b = blockIdx.x, t = threadIdx.x;
    int base = b * SCAN_CHUNK;
    int v[4]; int s = 0;
    #pragma unroll
    for (int i = 0; i < 4; i++) {
        int idx = base + t * 4 + i;
        v[i] = (idx < NR) ? g_cnt[idx] : 0;
        s += v[i];
    }
    sh[t] = s; __syncthreads();
    for (int off = 1; off < 256; off <<= 1) {
        int cur = sh[t];
        int y = (t >= off) ? sh[t - off] : 0;
        __syncthreads();
        sh[t] = cur + y;
        __syncthreads();
    }
    int run = g_bsums[b] + sh[t] - s;
    #pragma unroll
    for (int i = 0; i < 4; i++) {
        int idx = base + t * 4 + i;
        if (idx < NR) g_rs[idx] = run;
        run += v[i];
    }
}

__global__ void k_fill() {
    int i = blockIdx.x * blockDim.x + threadIdx.x;
    if (i >= N_EDGES) return;
    int seg = g_dst[i] * R + g_typ[i];
    int pos = atomicAdd(&g_fill[seg], 1);
    g_csr[g_rs[seg] + pos] = g_src[i];
}

// ----------------------------- feature encoder -----------------------------
__global__ void k_encode(const float* __restrict__ des, const float* __restrict__ twt,
                         const float* __restrict__ nump, const float* __restrict__ catp,
                         const float* __restrict__ Wd, const float* __restrict__ bd,
                         const float* __restrict__ Wt, const float* __restrict__ bt,
                         const float* __restrict__ Wn, const float* __restrict__ bn,
                         const float* __restrict__ Wc, const float* __restrict__ bc) {
    int n = blockIdx.x;
    __shared__ float sin[224];
    int t = threadIdx.x;
    if (t < 100) sin[t] = des[(size_t)n * 100 + t];
    for (int i = t; i < 100; i += 128) sin[100 + i] = twt[(size_t)n * 100 + i];
    if (t < 6)  sin[200 + t] = nump[(size_t)n * 6 + t];
    if (t < 11) sin[206 + t] = catp[(size_t)n * 11 + t];
    __syncthreads();

    int q = t >> 5, j = t & 31;
    const float* W; const float* b; const float* in; int fan;
    if (q == 0)      { W = Wd; b = bd; in = sin;       fan = 100; }
    else if (q == 1) { W = Wt; b = bt; in = sin + 100; fan = 100; }
    else if (q == 2) { W = Wn; b = bn; in = sin + 200; fan = 6;   }
    else             { W = Wc; b = bc; in = sin + 206; fan = 11;  }
    float acc = b[j];
    for (int k = 0; k < fan; k++) acc = fmaf(in[k], W[k * 32 + j], acc);
    acc = acc > 0.f ? acc : 0.01f * acc;
    g_XA[(size_t)n * D + t] = acc;
}

// ----------------------------- weight pack (all transposes in one kernel) --
__global__ void k_packAll(const float* __restrict__ W_in, const float* __restrict__ W_o1,
                          const float* __restrict__ W_rel, const float* __restrict__ W_root) {
    int i = blockIdx.x * blockDim.x + threadIdx.x;
    if (i >= 5 * 16384) return;
    int reg = i >> 14, r = i & 16383;
    int k = r >> 7, n = r & 127;
    if (reg == 0)      g_WinT[n * 128 + k] = W_in[r];
    else if (reg == 1) g_Wo1T[n * 128 + k] = W_o1[r];
    else if (reg == 2) g_WstkT[n * 384 + k]       = W_rel[r];
    else if (reg == 3) g_WstkT[n * 384 + 128 + k] = W_rel[16384 + r];
    else               g_WstkT[n * 384 + 256 + k] = W_root[r];
}

// ----------------------------- fp16 mma.sync GEMM (fp32 accum) -------------
// C[M,128] = A[M,kTot] @ Bt[128,kTot]^T + bias (optional lrelu).
// If out2 != nullptr: fused final projection to 2 classes via Wo2/bo2.
// A = A1 rows for k<kSplit else A2 (concat along K). 256 threads, tile 128x128,
// 8 warps as 4(m) x 2(n), each warp 32x64. K-slabs of 32 (2x m16n8k16).
// smem rows hold 16 half2 words per 32-K slab, padded stride 20 (bank-clean).

#define SGS 20   // padded row stride in 4B words (16 data half2 + 4 pad)

__device__ __forceinline__ unsigned f2h2(float lo, float hi) {
    unsigned r;
    asm("cvt.rn.f16x2.f32 %0, %1, %2;" : "=r"(r) : "f"(hi), "f"(lo));
    return r;
}

__device__ __forceinline__ void mma_f16(float* c, const unsigned* a,
                                        unsigned b0, unsigned b1) {
    asm volatile(
        "mma.sync.aligned.m16n8k16.row.col.f32.f16.f16.f32 "
        "{%0,%1,%2,%3}, {%4,%5,%6,%7}, {%8,%9}, {%0,%1,%2,%3};"
        : "+f"(c[0]), "+f"(c[1]), "+f"(c[2]), "+f"(c[3])
        : "r"(a[0]), "r"(a[1]), "r"(a[2]), "r"(a[3]), "r"(b0), "r"(b1));
}

__global__ __launch_bounds__(256) void k_gemm_tc(
    const float* __restrict__ A1, int ldA1,
    const float* __restrict__ A2, int ldA2,
    int kSplit, int kTot,
    const float* __restrict__ Bt,
    float* __restrict__ C, int M,
    const float* __restrict__ bias, int act,
    const float* __restrict__ Wo2, const float* __restrict__ bo2,
    float* __restrict__ out2)
{
    __shared__ unsigned sA[128 * SGS];
    __shared__ unsigned sB[128 * SGS];

    int tid = threadIdx.x;
    int wid = tid >> 5, lane = tid & 31;
    int gid = lane >> 2, tig = lane & 3;
    int warp_m = wid & 3, warp_n = wid >> 2;
    int bm = blockIdx.x * 128;

    int srow = tid >> 1;          // staging row 0..127
    int shalf = tid & 1;          // which 16-float half of the 32-slab
    int arow = bm + srow; if (arow > M - 1) arow = M - 1;

    float acc[2][8][4];
    #pragma unroll
    for (int i = 0; i < 2; i++)
        #pragma unroll
        for (int j = 0; j < 8; j++)
            #pragma unroll
            for (int q = 0; q < 4; q++) acc[i][j][q] = 0.f;

    int nSlab = kTot >> 5;
    for (int s = 0; s < nSlab; s++) {
        int k0 = s << 5;
        const float* asrc = (k0 < kSplit)
            ? A1 + (size_t)arow * ldA1 + k0 + shalf * 16
            : A2 + (size_t)arow * ldA2 + (k0 - kSplit) + shalf * 16;
        #pragma unroll
        for (int j = 0; j < 4; j++) {
            float4 v = *(const float4*)(asrc + j * 4);
            int o = srow * SGS + shalf * 8 + j * 2;
            *(uint2*)(sA + o) = make_uint2(f2h2(v.x, v.y), f2h2(v.z, v.w));
        }
        const float* bsrc = Bt + (size_t)srow * kTot + k0 + shalf * 16;
        #pragma unroll
        for (int j = 0; j < 4; j++) {
            float4 v = *(const float4*)(bsrc + j * 4);
            int o = srow * SGS + shalf * 8 + j * 2;
            *(uint2*)(sB + o) = make_uint2(f2h2(v.x, v.y), f2h2(v.z, v.w));
        }
        __syncthreads();

        #pragma unroll
        for (int kk = 0; kk < 2; kk++) {
            int kw = (kk << 3) + tig;
            unsigned ah[2][4];
            #pragma unroll
            for (int mf = 0; mf < 2; mf++) {
                int r0 = (warp_m * 32 + mf * 16 + gid) * SGS + kw;
                int r1 = r0 + 8 * SGS;
                ah[mf][0] = sA[r0]; ah[mf][1] = sA[r1];
                ah[mf][2] = sA[r0 + 4]; ah[mf][3] = sA[r1 + 4];
            }
            #pragma unroll
            for (int nf = 0; nf < 8; nf++) {
                int nb = (warp_n * 64 + nf * 8 + gid) * SGS + kw;
                unsigned b0 = sB[nb], b1 = sB[nb + 4];
                #pragma unroll
                for (int mf = 0; mf < 2; mf++)
                    mma_f16(acc[mf][nf], ah[mf], b0, b1);
            }
        }
        __syncthreads();
    }

    if (out2 == nullptr) {
        // ---- standard epilogue: bias (+lrelu) and store C ----
        #pragma unroll
        for (int mf = 0; mf < 2; mf++) {
            int r0 = bm + warp_m * 32 + mf * 16 + gid;
            int r1 = r0 + 8;
            #pragma unroll
            for (int nf = 0; nf < 8; nf++) {
                int c = warp_n * 64 + nf * 8 + tig * 2;
                float b0 = bias[c], b1 = bias[c + 1];
                float v0 = acc[mf][nf][0] + b0, v1 = acc[mf][nf][1] + b1;
                float v2 = acc[mf][nf][2] + b0, v3 = acc[mf][nf][3] + b1;
                if (act) {
                    v0 = v0 > 0.f ? v0 : 0.01f * v0;
                    v1 = v1 > 0.f ? v1 : 0.01f * v1;
                    v2 = v2 > 0.f ? v2 : 0.01f * v2;
                    v3 = v3 > 0.f ? v3 : 0.01f * v3;
                }
                if (r0 < M) *(float2*)(C + (size_t)r0 * 128 + c) = make_float2(v0, v1);
                if (r1 < M) *(float2*)(C + (size_t)r1 * 128 + c) = make_float2(v2, v3);
            }
        }
    } else {
        // ---- fused final projection: out2[r] = lrelu(C_row+bias) @ Wo2 + bo2 ----
        float p[2][2][2] = {{{0.f,0.f},{0.f,0.f}},{{0.f,0.f},{0.f,0.f}}};
        #pragma unroll
        for (int mf = 0; mf < 2; mf++) {
            #pragma unroll
            for (int nf = 0; nf < 8; nf++) {
                int c = warp_n * 64 + nf * 8 + tig * 2;
                float b0 = bias[c], b1 = bias[c + 1];
                float v0 = acc[mf][nf][0] + b0, v1 = acc[mf][nf][1] + b1;
                float v2 = acc[mf][nf][2] + b0, v3 = acc[mf][nf][3] + b1;
                if (act) {
                    v0 = v0 > 0.f ? v0 : 0.01f * v0;
                    v1 = v1 > 0.f ? v1 : 0.01f * v1;
                    v2 = v2 > 0.f ? v2 : 0.01f * v2;
                    v3 = v3 > 0.f ? v3 : 0.01f * v3;
                }
                float w00 = Wo2[c * 2 + 0], w01 = Wo2[c * 2 + 1];
                float w10 = Wo2[c * 2 + 2], w11 = Wo2[c * 2 + 3];
                p[mf][0][0] = fmaf(v0, w00, fmaf(v1, w10, p[mf][0][0]));
                p[mf][0][1] = fmaf(v0, w01, fmaf(v1, w11, p[mf][0][1]));
                p[mf][1][0] = fmaf(v2, w00, fmaf(v3, w10, p[mf][1][0]));
                p[mf][1][1] = fmaf(v2, w01, fmaf(v3, w11, p[mf][1][1]));
            }
        }
        #pragma unroll
        for (int m = 1; m < 4; m <<= 1) {
            #pragma unroll
            for (int mf = 0; mf < 2; mf++)
                #pragma unroll
                for (int h = 0; h < 2; h++)
                    #pragma unroll
                    for (int j = 0; j < 2; j++)
                        p[mf][h][j] += __shfl_xor_sync(0xFFFFFFFFu, p[mf][h][j], m);
        }
        __syncthreads();
        float* sRed = (float*)sA;   // 256 floats used
        if (warp_n == 0 && tig == 0) {
            #pragma unroll
            for (int mf = 0; mf < 2; mf++)
                #pragma unroll
                for (int h = 0; h < 2; h++) {
                    int rid = warp_m * 32 + mf * 16 + h * 8 + gid;
                    sRed[rid * 2 + 0] = p[mf][h][0];
                    sRed[rid * 2 + 1] = p[mf][h][1];
                }
        }
        __syncthreads();
        if (warp_n == 1 && tig == 0) {
            #pragma unroll
            for (int mf = 0; mf < 2; mf++)
                #pragma unroll
                for (int h = 0; h < 2; h++) {
                    int rid = warp_m * 32 + mf * 16 + h * 8 + gid;
                    int row = bm + rid;
                    if (row < M) {
                        out2[(size_t)row * 2 + 0] = p[mf][h][0] + sRed[rid * 2 + 0] + bo2[0];
                        out2[(size_t)row * 2 + 1] = p[mf][h][1] + sRed[rid * 2 + 1] + bo2[1];
                    }
                }
        }
    }
}

// ----------------------------- aggregation (mean per (node,rel) from X) ----
__global__ void k_agg2(const float* __restrict__ X, float* __restrict__ Mout) {
    int w = (blockIdx.x * blockDim.x + threadIdx.x) >> 5;
    if (w >= NR) return;
    int lane = threadIdx.x & 31;
    int n = w >> 1, rel = w & 1;
    int s = g_rs[w], e = g_rs[w + 1];
    float4 sum = make_float4(0.f, 0.f, 0.f, 0.f);
    int i = s;
    for (; i + 4 <= e; i += 4) {
        int i0 = g_csr[i], i1 = g_csr[i + 1], i2 = g_csr[i + 2], i3 = g_csr[i + 3];
        float4 a = ((const float4*)(X + (size_t)i0 * D))[lane];
        float4 b = ((const float4*)(X + (size_t)i1 * D))[lane];
        float4 c = ((const float4*)(X + (size_t)i2 * D))[lane];
        float4 d = ((const float4*)(X + (size_t)i3 * D))[lane];
        sum.x += a.x + b.x + c.x + d.x;
        sum.y += a.y + b.y + c.y + d.y;
        sum.z += a.z + b.z + c.z + d.z;
        sum.w += a.w + b.w + c.w + d.w;
    }
    for (; i < e; i++) {
        float4 a = ((const float4*)(X + (size_t)g_csr[i] * D))[lane];
        sum.x += a.x; sum.y += a.y; sum.z += a.z; sum.w += a.w;
    }
    float inv = (e > s) ? 1.0f / (float)(e - s) : 0.0f;
    sum.x *= inv; sum.y *= inv; sum.z *= inv; sum.w *= inv;
    ((float4*)(Mout + (size_t)n * 256 + rel * D))[lane] = sum;
}

// ----------------------------- launch --------------------------------------
extern "C" void kernel_launch(void* const* d_in, const int* in_sizes, int n_in,
                              void* d_out, int out_size) {
    const float* des   = (const float*)d_in[0];
    const float* twt   = (const float*)d_in[1];
    const float* nump  = (const float*)d_in[2];
    const float* catp  = (const float*)d_in[3];
    const void*  ei    = d_in[4];
    const void*  et    = d_in[5];
    const float* Wd    = (const float*)d_in[6];
    const float* bd    = (const float*)d_in[7];
    const float* Wt    = (const float*)d_in[8];
    const float* bt    = (const float*)d_in[9];
    const float* Wn    = (const float*)d_in[10];
    const float* bn    = (const float*)d_in[11];
    const float* Wc    = (const float*)d_in[12];
    const float* bc    = (const float*)d_in[13];
    const float* W_in  = (const float*)d_in[14];
    const float* b_in  = (const float*)d_in[15];
    const float* W_rel = (const float*)d_in[16];
    const float* W_root= (const float*)d_in[17];
    const float* b_rg  = (const float*)d_in[18];
    const float* W_o1  = (const float*)d_in[19];
    const float* b_o1  = (const float*)d_in[20];
    const float* W_o2  = (const float*)d_in[21];
    const float* b_o2  = (const float*)d_in[22];
    float* out = (float*)d_out;

    float *XA, *XB, *Mg, *WinT, *Wo1T, *WstkT;
    cudaGetSymbolAddress((void**)&XA, g_XA);
    cudaGetSymbolAddress((void**)&XB, g_XB);
    cudaGetSymbolAddress((void**)&Mg, g_M);
    cudaGetSymbolAddress((void**)&WinT, g_WinT);
    cudaGetSymbolAddress((void**)&Wo1T, g_Wo1T);
    cudaGetSymbolAddress((void**)&WstkT, g_WstkT);

    const int TB = 256;
    int ceb = (N_EDGES + TB - 1) / TB;
    int gGemm = (N_NODES + 127) / 128;      // 782
    int gAgg  = (NR * 32 + TB - 1) / TB;    // 25000

    // side stream for the independent CSR-build chain (leaked; few calls total)
    cudaStream_t s2;
    cudaEvent_t evRoot, evB;
    cudaStreamCreateWithFlags(&s2, cudaStreamNonBlocking);
    cudaEventCreateWithFlags(&evRoot, cudaEventDisableTiming);
    cudaEventCreateWithFlags(&evB, cudaEventDisableTiming);

    cudaEventRecord(evRoot, 0);
    cudaStreamWaitEvent(s2, evRoot, 0);

    // --- main stream: encode -> pack -> GEMM1 (gemm is 4th submission: profiled) ---
    k_encode<<<N_NODES, 128>>>(des, twt, nump, catp, Wd, bd, Wt, bt, Wn, bn, Wc, bc);
    k_packAll<<<(5 * 16384 + TB - 1) / TB, TB>>>(W_in, W_o1, W_rel, W_root);
    k_zero_seg<<<(NR + TB - 1) / TB, TB, 0, s2>>>();
    k_gemm_tc<<<gGemm, 256>>>(XA, 128, XA, 128, 128, 128, WinT, XB, N_NODES, b_in, 1,
                              nullptr, nullptr, nullptr);

    // --- side stream: CSR build (overlaps the above) ---
    k_detect<<<1, 64, 0, s2>>>((const unsigned int*)ei, (const unsigned int*)et);
    k_convert_hist<<<ceb, TB, 0, s2>>>(ei, et);
    k_scan1<<<SCAN_NB, 256, 0, s2>>>();
    k_scan2<<<1, 256, 0, s2>>>();
    k_scan3<<<SCAN_NB, 256, 0, s2>>>();
    k_fill<<<ceb, TB, 0, s2>>>();
    cudaEventRecord(evB, s2);
    cudaStreamWaitEvent(0, evB, 0);

    // RGCN layer 1: M = means(XB); XA = [M|XB] @ WstkT^T + b_rg
    k_agg2<<<gAgg, TB>>>(XB, Mg);
    k_gemm_tc<<<gGemm, 256>>>(Mg, 256, XB, 128, 256, 384, WstkT, XA, N_NODES, b_rg, 0,
                              nullptr, nullptr, nullptr);

    // RGCN layer 2: M = means(XA); XB = [M|XA] @ WstkT^T + b_rg
    k_agg2<<<gAgg, TB>>>(XA, Mg);
    k_gemm_tc<<<gGemm, 256>>>(Mg, 256, XA, 128, 256, 384, WstkT, XB, N_NODES, b_rg, 0,
                              nullptr, nullptr, nullptr);

    // fused: out = lrelu(XB @ Wo1 + b_o1) @ W_o2 + b_o2
    k_gemm_tc<<<gGemm, 256>>>(XB, 128, XB, 128, 128, 128, Wo1T, XA, N_NODES, b_o1, 1,
                              W_o2, b_o2, out);
}

// round 9
// speedup vs baseline: 2.7013x; 1.2515x over previous
#include <cuda_runtime.h>
#include <cuda_fp16.h>
#include <cstdint>

#define N_NODES 100000
#define N_EDGES 1600000
#define D 128
#define R 2
#define NR (N_NODES * R)          // 200000 segments
#define SCAN_CHUNK 1024
#define SCAN_NB ((NR + SCAN_CHUNK - 1) / SCAN_CHUNK)   // 196

// ----------------------------- scratch (static device globals; no allocs) ---
__device__ __half g_X0h[(size_t)N_NODES * D];    // encoder out (fp16)
__device__ float  g_X1 [(size_t)N_NODES * D];    // gemm1 out fp32 (agg1 input)
__device__ __half g_X1h[(size_t)N_NODES * D];
__device__ float  g_X2 [(size_t)N_NODES * D];    // gemm2 out fp32 (agg2 input)
__device__ __half g_X2h[(size_t)N_NODES * D];
__device__ __half g_X3h[(size_t)N_NODES * D];    // gemm3 out (fp16 only)
__device__ __half g_Mh [(size_t)N_NODES * 256];  // [mean_rel0 | mean_rel1] fp16
__device__ __half g_WinTh[D * D];
__device__ __half g_Wo1Th[D * D];
__device__ __half g_WstkTh[D * 384];
__device__ int   g_src[N_EDGES];
__device__ int   g_dst[N_EDGES];
__device__ int   g_typ[N_EDGES];
__device__ int   g_cnt[NR];
__device__ int   g_fill[NR];
__device__ int   g_rs[NR + 1];
__device__ int   g_bsums[256];
__device__ int   g_flag[2];
__device__ int   g_csr[N_EDGES];

// ----------------------------- dtype detection -----------------------------
__global__ void k_detect(const unsigned int* __restrict__ ei,
                         const unsigned int* __restrict__ et) {
    __shared__ int nz_i, nz_t;
    if (threadIdx.x == 0) { nz_i = 0; nz_t = 0; }
    __syncthreads();
    for (int i = threadIdx.x; i < 512; i += blockDim.x) {
        if (ei[2 * i + 1] != 0u) atomicOr(&nz_i, 1);
        if (et[2 * i + 1] != 0u) atomicOr(&nz_t, 1);
    }
    __syncthreads();
    if (threadIdx.x == 0) {
        g_flag[0] = (nz_i == 0) ? 1 : 0;
        g_flag[1] = (nz_t == 0) ? 1 : 0;
    }
}

// convert + histogram in one pass over the edge list
__global__ void k_convert_hist(const void* __restrict__ ei, const void* __restrict__ et) {
    int i = blockIdx.x * blockDim.x + threadIdx.x;
    if (i >= N_EDGES) return;
    int s, d, t;
    if (g_flag[0]) {
        const long long* p = (const long long*)ei;
        s = (int)p[i]; d = (int)p[(size_t)N_EDGES + i];
    } else {
        const int* p = (const int*)ei;
        s = p[i]; d = p[N_EDGES + i];
    }
    if (g_flag[1]) t = (int)((const long long*)et)[i];
    else           t = ((const int*)et)[i];
    g_src[i] = s; g_dst[i] = d; g_typ[i] = t;
    atomicAdd(&g_cnt[d * R + t], 1);
}

// ----------------------------- CSR build -----------------------------------
__global__ void k_zero_seg() {
    int i = blockIdx.x * blockDim.x + threadIdx.x;
    if (i < NR) { g_cnt[i] = 0; g_fill[i] = 0; }
}

__global__ void k_scan1() {
    __shared__ int sh[256];
    int b = blockIdx.x, t = threadIdx.x;
    int s = 0;
    #pragma unroll
    for (int i = 0; i < 4; i++) {
        int idx = b * SCAN_CHUNK + t * 4 + i;
        if (idx < NR) s += g_cnt[idx];
    }
    sh[t] = s; __syncthreads();
    for (int off = 128; off > 0; off >>= 1) {
        if (t < off) sh[t] += sh[t + off];
        __syncthreads();
    }
    if (t == 0) g_bsums[b] = sh[0];
}

__global__ void k_scan2() {
    __shared__ int sh[256];
    int t = threadIdx.x;
    sh[t] = (t < SCAN_NB) ? g_bsums[t] : 0;
    __syncthreads();
    if (t == 0) {
        int run = 0;
        for (int i = 0; i < SCAN_NB; i++) { int c = sh[i]; sh[i] = run; run += c; }
        g_rs[NR] = N_EDGES;
    }
    __syncthreads();
    if (t < SCAN_NB) g_bsums[t] = sh[t];
}

__global__ void k_scan3() {
    __shared__ int sh[256];
    int b = blockIdx.x, t = threadIdx.x;
    int base = b * SCAN_CHUNK;
    int v[4]; int s = 0;
    #pragma unroll
    for (int i = 0; i < 4; i++) {
        int idx = base + t * 4 + i;
        v[i] = (idx < NR) ? g_cnt[idx] : 0;
        s += v[i];
    }
    sh[t] = s; __syncthreads();
    for (int off = 1; off < 256; off <<= 1) {
        int cur = sh[t];
        int y = (t >= off) ? sh[t - off] : 0;
        __syncthreads();
        sh[t] = cur + y;
        __syncthreads();
    }
    int run = g_bsums[b] + sh[t] - s;
    #pragma unroll
    for (int i = 0; i < 4; i++) {
        int idx = base + t * 4 + i;
        if (idx < NR) g_rs[idx] = run;
        run += v[i];
    }
}

__global__ void k_fill() {
    int i = blockIdx.x * blockDim.x + threadIdx.x;
    if (i >= N_EDGES) return;
    int seg = g_dst[i] * R + g_typ[i];
    int pos = atomicAdd(&g_fill[seg], 1);
    g_csr[g_rs[seg] + pos] = g_src[i];
}

// ----------------------------- feature encoder (fp16 out) ------------------
__global__ void k_encode(const float* __restrict__ des, const float* __restrict__ twt,
                         const float* __restrict__ nump, const float* __restrict__ catp,
                         const float* __restrict__ Wd, const float* __restrict__ bd,
                         const float* __restrict__ Wt, const float* __restrict__ bt,
                         const float* __restrict__ Wn, const float* __restrict__ bn,
                         const float* __restrict__ Wc, const float* __restrict__ bc) {
    int n = blockIdx.x;
    __shared__ float sin[224];
    int t = threadIdx.x;
    if (t < 100) sin[t] = des[(size_t)n * 100 + t];
    for (int i = t; i < 100; i += 128) sin[100 + i] = twt[(size_t)n * 100 + i];
    if (t < 6)  sin[200 + t] = nump[(size_t)n * 6 + t];
    if (t < 11) sin[206 + t] = catp[(size_t)n * 11 + t];
    __syncthreads();

    int q = t >> 5, j = t & 31;
    const float* W; const float* b; const float* in; int fan;
    if (q == 0)      { W = Wd; b = bd; in = sin;       fan = 100; }
    else if (q == 1) { W = Wt; b = bt; in = sin + 100; fan = 100; }
    else if (q == 2) { W = Wn; b = bn; in = sin + 200; fan = 6;   }
    else             { W = Wc; b = bc; in = sin + 206; fan = 11;  }
    float acc = b[j];
    for (int k = 0; k < fan; k++) acc = fmaf(in[k], W[k * 32 + j], acc);
    acc = acc > 0.f ? acc : 0.01f * acc;
    g_X0h[(size_t)n * D + t] = __float2half_rn(acc);
}

// ----------------------------- weight pack (fp16 transposed) ---------------
__global__ void k_packAll(const float* __restrict__ W_in, const float* __restrict__ W_o1,
                          const float* __restrict__ W_rel, const float* __restrict__ W_root) {
    int i = blockIdx.x * blockDim.x + threadIdx.x;
    if (i >= 5 * 16384) return;
    int reg = i >> 14, r = i & 16383;
    int k = r >> 7, n = r & 127;
    if (reg == 0)      g_WinTh[n * 128 + k] = __float2half_rn(W_in[r]);
    else if (reg == 1) g_Wo1Th[n * 128 + k] = __float2half_rn(W_o1[r]);
    else if (reg == 2) g_WstkTh[n * 384 + k]       = __float2half_rn(W_rel[r]);
    else if (reg == 3) g_WstkTh[n * 384 + 128 + k] = __float2half_rn(W_rel[16384 + r]);
    else               g_WstkTh[n * 384 + 256 + k] = __float2half_rn(W_root[r]);
}

// ----------------------------- fp16 mma GEMM: cp.async + ldmatrix ----------
// C/Ch[M,128] = A[M,kTot] @ Bt[128,kTot]^T + bias (optional lrelu).
// A (fp16) = A1 rows for k<kSplit else A2. 256 threads, tile 128x128,
// 8 warps 4(m)x2(n), warp 32x64, K-slab 32, double-buffered cp.async,
// smem row stride 40 halfs (80B: conflict-free ldmatrix).

#define RS 40   // smem row stride in halfs

__device__ __forceinline__ unsigned f2h2(float lo, float hi) {
    unsigned r;
    asm("cvt.rn.f16x2.f32 %0, %1, %2;" : "=r"(r) : "f"(hi), "f"(lo));
    return r;
}

__device__ __forceinline__ void cpa16(uint32_t dst, const void* src) {
    asm volatile("cp.async.cg.shared.global [%0], [%1], 16;" :: "r"(dst), "l"(src));
}

__device__ __forceinline__ void mma_f16(float* c, const unsigned* a,
                                        unsigned b0, unsigned b1) {
    asm volatile(
        "mma.sync.aligned.m16n8k16.row.col.f32.f16.f16.f32 "
        "{%0,%1,%2,%3}, {%4,%5,%6,%7}, {%8,%9}, {%0,%1,%2,%3};"
        : "+f"(c[0]), "+f"(c[1]), "+f"(c[2]), "+f"(c[3])
        : "r"(a[0]), "r"(a[1]), "r"(a[2]), "r"(a[3]), "r"(b0), "r"(b1));
}

__device__ __forceinline__ void stage_slab(
    uint32_t sAb, uint32_t sBb,
    const __half* __restrict__ A1, int ldA1,
    const __half* __restrict__ A2, int ldA2, int kSplit,
    const __half* __restrict__ Bt, int kTot,
    int k0, int bm, int M, int tid)
{
    #pragma unroll
    for (int i = 0; i < 2; i++) {
        int c = tid + i * 256;            // 0..511
        int row = c >> 2, ch = c & 3;
        int grow = bm + row; if (grow > M - 1) grow = M - 1;
        const __half* src = (k0 < kSplit)
            ? A1 + (size_t)grow * ldA1 + k0 + ch * 8
            : A2 + (size_t)grow * ldA2 + (k0 - kSplit) + ch * 8;
        cpa16(sAb + (row * RS + ch * 8) * 2, src);
    }
    #pragma unroll
    for (int i = 0; i < 2; i++) {
        int c = tid + i * 256;
        int row = c >> 2, ch = c & 3;
        const __half* src = Bt + (size_t)row * kTot + k0 + ch * 8;
        cpa16(sBb + (row * RS + ch * 8) * 2, src);
    }
    asm volatile("cp.async.commit_group;");
}

__global__ __launch_bounds__(256) void k_gemm_tc(
    const __half* __restrict__ A1, int ldA1,
    const __half* __restrict__ A2, int ldA2,
    int kSplit, int kTot,
    const __half* __restrict__ Bt,
    float* __restrict__ C, __half* __restrict__ Ch, int M,
    const float* __restrict__ bias, int act,
    const float* __restrict__ Wo2, const float* __restrict__ bo2,
    float* __restrict__ out2)
{
    __shared__ __half sA[2][128 * RS];
    __shared__ __half sB[2][128 * RS];

    int tid = threadIdx.x;
    int wid = tid >> 5, lane = tid & 31;
    int gid = lane >> 2, tig = lane & 3;
    int lg = lane >> 3, lr = lane & 7;
    int warp_m = wid & 3, warp_n = wid >> 2;
    int bm = blockIdx.x * 128;

    uint32_t sA0 = (uint32_t)__cvta_generic_to_shared(&sA[0][0]);
    uint32_t sA1 = (uint32_t)__cvta_generic_to_shared(&sA[1][0]);
    uint32_t sB0 = (uint32_t)__cvta_generic_to_shared(&sB[0][0]);
    uint32_t sB1 = (uint32_t)__cvta_generic_to_shared(&sB[1][0]);

    float acc[2][8][4];
    #pragma unroll
    for (int i = 0; i < 2; i++)
        #pragma unroll
        for (int j = 0; j < 8; j++)
            #pragma unroll
            for (int q = 0; q < 4; q++) acc[i][j][q] = 0.f;

    int nSlab = kTot >> 5;
    stage_slab(sA0, sB0, A1, ldA1, A2, ldA2, kSplit, Bt, kTot, 0, bm, M, tid);

    for (int s = 0; s < nSlab; s++) {
        asm volatile("cp.async.wait_group 0;");
        __syncthreads();
        if (s + 1 < nSlab) {
            uint32_t nb = (s + 1) & 1;
            stage_slab(nb ? sA1 : sA0, nb ? sB1 : sB0,
                       A1, ldA1, A2, ldA2, kSplit, Bt, kTot,
                       (s + 1) << 5, bm, M, tid);
        }
        uint32_t bf = s & 1;
        uint32_t sAb = bf ? sA1 : sA0;
        uint32_t sBb = bf ? sB1 : sB0;

        #pragma unroll
        for (int kk = 0; kk < 2; kk++) {
            unsigned af[2][4];
            #pragma unroll
            for (int mf = 0; mf < 2; mf++) {
                int row = warp_m * 32 + mf * 16 + ((lg & 1) << 3) + lr;
                int col = (kk << 4) + ((lg >> 1) << 3);
                uint32_t ad = sAb + (uint32_t)(row * RS + col) * 2;
                asm volatile(
                    "ldmatrix.sync.aligned.m8n8.x4.shared.b16 {%0,%1,%2,%3}, [%4];"
                    : "=r"(af[mf][0]), "=r"(af[mf][1]), "=r"(af[mf][2]), "=r"(af[mf][3])
                    : "r"(ad));
            }
            #pragma unroll
            for (int np = 0; np < 4; np++) {
                int row = warp_n * 64 + np * 16 + ((lg >> 1) << 3) + lr;
                int col = (kk << 4) + ((lg & 1) << 3);
                uint32_t bd = sBb + (uint32_t)(row * RS + col) * 2;
                unsigned b0, b1, b2, b3;
                asm volatile(
                    "ldmatrix.sync.aligned.m8n8.x4.shared.b16 {%0,%1,%2,%3}, [%4];"
                    : "=r"(b0), "=r"(b1), "=r"(b2), "=r"(b3) : "r"(bd));
                mma_f16(acc[0][2 * np],     af[0], b0, b1);
                mma_f16(acc[1][2 * np],     af[1], b0, b1);
                mma_f16(acc[0][2 * np + 1], af[0], b2, b3);
                mma_f16(acc[1][2 * np + 1], af[1], b2, b3);
            }
        }
    }

    if (out2 == nullptr) {
        // ---- epilogue: bias (+lrelu), store fp32 C and/or fp16 Ch ----
        #pragma unroll
        for (int mf = 0; mf < 2; mf++) {
            int r0 = bm + warp_m * 32 + mf * 16 + gid;
            int r1 = r0 + 8;
            #pragma unroll
            for (int nf = 0; nf < 8; nf++) {
                int c = warp_n * 64 + nf * 8 + tig * 2;
                float b0 = bias[c], b1 = bias[c + 1];
                float v0 = acc[mf][nf][0] + b0, v1 = acc[mf][nf][1] + b1;
                float v2 = acc[mf][nf][2] + b0, v3 = acc[mf][nf][3] + b1;
                if (act) {
                    v0 = v0 > 0.f ? v0 : 0.01f * v0;
                    v1 = v1 > 0.f ? v1 : 0.01f * v1;
                    v2 = v2 > 0.f ? v2 : 0.01f * v2;
                    v3 = v3 > 0.f ? v3 : 0.01f * v3;
                }
                if (r0 < M) {
                    if (C)  *(float2*)(C + (size_t)r0 * 128 + c) = make_float2(v0, v1);
                    if (Ch) *(unsigned*)(Ch + (size_t)r0 * 128 + c) = f2h2(v0, v1);
                }
                if (r1 < M) {
                    if (C)  *(float2*)(C + (size_t)r1 * 128 + c) = make_float2(v2, v3);
                    if (Ch) *(unsigned*)(Ch + (size_t)r1 * 128 + c) = f2h2(v2, v3);
                }
            }
        }
    } else {
        // ---- fused final projection: out2[r] = lrelu(C_row+bias) @ Wo2 + bo2 ----
        float p[2][2][2] = {{{0.f,0.f},{0.f,0.f}},{{0.f,0.f},{0.f,0.f}}};
        #pragma unroll
        for (int mf = 0; mf < 2; mf++) {
            #pragma unroll
            for (int nf = 0; nf < 8; nf++) {
                int c = warp_n * 64 + nf * 8 + tig * 2;
                float b0 = bias[c], b1 = bias[c + 1];
                float v0 = acc[mf][nf][0] + b0, v1 = acc[mf][nf][1] + b1;
                float v2 = acc[mf][nf][2] + b0, v3 = acc[mf][nf][3] + b1;
                if (act) {
                    v0 = v0 > 0.f ? v0 : 0.01f * v0;
                    v1 = v1 > 0.f ? v1 : 0.01f * v1;
                    v2 = v2 > 0.f ? v2 : 0.01f * v2;
                    v3 = v3 > 0.f ? v3 : 0.01f * v3;
                }
                float w00 = Wo2[c * 2 + 0], w01 = Wo2[c * 2 + 1];
                float w10 = Wo2[c * 2 + 2], w11 = Wo2[c * 2 + 3];
                p[mf][0][0] = fmaf(v0, w00, fmaf(v1, w10, p[mf][0][0]));
                p[mf][0][1] = fmaf(v0, w01, fmaf(v1, w11, p[mf][0][1]));
                p[mf][1][0] = fmaf(v2, w00, fmaf(v3, w10, p[mf][1][0]));
                p[mf][1][1] = fmaf(v2, w01, fmaf(v3, w11, p[mf][1][1]));
            }
        }
        #pragma unroll
        for (int m = 1; m < 4; m <<= 1) {
            #pragma unroll
            for (int mf = 0; mf < 2; mf++)
                #pragma unroll
                for (int h = 0; h < 2; h++)
                    #pragma unroll
                    for (int j = 0; j < 2; j++)
                        p[mf][h][j] += __shfl_xor_sync(0xFFFFFFFFu, p[mf][h][j], m);
        }
        __syncthreads();
        float* sRed = (float*)&sA[0][0];   // 256 floats reused
        if (warp_n == 0 && tig == 0) {
            #pragma unroll
            for (int mf = 0; mf < 2; mf++)
                #pragma unroll
                for (int h = 0; h < 2; h++) {
                    int rid = warp_m * 32 + mf * 16 + h * 8 + gid;
                    sRed[rid * 2 + 0] = p[mf][h][0];
                    sRed[rid * 2 + 1] = p[mf][h][1];
                }
        }
        __syncthreads();
        if (warp_n == 1 && tig == 0) {
            #pragma unroll
            for (int mf = 0; mf < 2; mf++)
                #pragma unroll
                for (int h = 0; h < 2; h++) {
                    int rid = warp_m * 32 + mf * 16 + h * 8 + gid;
                    int row = bm + rid;
                    if (row < M) {
                        out2[(size_t)row * 2 + 0] = p[mf][h][0] + sRed[rid * 2 + 0] + bo2[0];
                        out2[(size_t)row * 2 + 1] = p[mf][h][1] + sRed[rid * 2 + 1] + bo2[1];
                    }
                }
        }
    }
}

// ----------------------------- aggregation (fp32 in, fp16 means out) -------
__global__ void k_agg2(const float* __restrict__ X, __half* __restrict__ Mh) {
    int w = (blockIdx.x * blockDim.x + threadIdx.x) >> 5;
    if (w >= NR) return;
    int lane = threadIdx.x & 31;
    int n = w >> 1, rel = w & 1;
    int s = g_rs[w], e = g_rs[w + 1];
    float4 sum = make_float4(0.f, 0.f, 0.f, 0.f);
    int i = s;
    for (; i + 4 <= e; i += 4) {
        int i0 = g_csr[i], i1 = g_csr[i + 1], i2 = g_csr[i + 2], i3 = g_csr[i + 3];
        float4 a = ((const float4*)(X + (size_t)i0 * D))[lane];
        float4 b = ((const float4*)(X + (size_t)i1 * D))[lane];
        float4 c = ((const float4*)(X + (size_t)i2 * D))[lane];
        float4 d = ((const float4*)(X + (size_t)i3 * D))[lane];
        sum.x += a.x + b.x + c.x + d.x;
        sum.y += a.y + b.y + c.y + d.y;
        sum.z += a.z + b.z + c.z + d.z;
        sum.w += a.w + b.w + c.w + d.w;
    }
    for (; i < e; i++) {
        float4 a = ((const float4*)(X + (size_t)g_csr[i] * D))[lane];
        sum.x += a.x; sum.y += a.y; sum.z += a.z; sum.w += a.w;
    }
    float inv = (e > s) ? 1.0f / (float)(e - s) : 0.0f;
    sum.x *= inv; sum.y *= inv; sum.z *= inv; sum.w *= inv;
    unsigned u0 = f2h2(sum.x, sum.y), u1 = f2h2(sum.z, sum.w);
    *(uint2*)(Mh + (size_t)n * 256 + rel * D + lane * 4) = make_uint2(u0, u1);
}

// ----------------------------- launch --------------------------------------
extern "C" void kernel_launch(void* const* d_in, const int* in_sizes, int n_in,
                              void* d_out, int out_size) {
    const float* des   = (const float*)d_in[0];
    const float* twt   = (const float*)d_in[1];
    const float* nump  = (const float*)d_in[2];
    const float* catp  = (const float*)d_in[3];
    const void*  ei    = d_in[4];
    const void*  et    = d_in[5];
    const float* Wd    = (const float*)d_in[6];
    const float* bd    = (const float*)d_in[7];
    const float* Wt    = (const float*)d_in[8];
    const float* bt    = (const float*)d_in[9];
    const float* Wn    = (const float*)d_in[10];
    const float* bn    = (const float*)d_in[11];
    const float* Wc    = (const float*)d_in[12];
    const float* bc    = (const float*)d_in[13];
    const float* W_in  = (const float*)d_in[14];
    const float* b_in  = (const float*)d_in[15];
    const float* W_rel = (const float*)d_in[16];
    const float* W_root= (const float*)d_in[17];
    const float* b_rg  = (const float*)d_in[18];
    const float* W_o1  = (const float*)d_in[19];
    const float* b_o1  = (const float*)d_in[20];
    const float* W_o2  = (const float*)d_in[21];
    const float* b_o2  = (const float*)d_in[22];
    float* out = (float*)d_out;

    float *X1, *X2;
    __half *X0h, *X1h, *X2h, *X3h, *Mh, *WinTh, *Wo1Th, *WstkTh;
    cudaGetSymbolAddress((void**)&X0h, g_X0h);
    cudaGetSymbolAddress((void**)&X1,  g_X1);
    cudaGetSymbolAddress((void**)&X1h, g_X1h);
    cudaGetSymbolAddress((void**)&X2,  g_X2);
    cudaGetSymbolAddress((void**)&X2h, g_X2h);
    cudaGetSymbolAddress((void**)&X3h, g_X3h);
    cudaGetSymbolAddress((void**)&Mh,  g_Mh);
    cudaGetSymbolAddress((void**)&WinTh,  g_WinTh);
    cudaGetSymbolAddress((void**)&Wo1Th,  g_Wo1Th);
    cudaGetSymbolAddress((void**)&WstkTh, g_WstkTh);

    const int TB = 256;
    int ceb = (N_EDGES + TB - 1) / TB;
    int gGemm = (N_NODES + 127) / 128;      // 782
    int gAgg  = (NR * 32 + TB - 1) / TB;    // 25000

    // side stream for the independent CSR-build chain (leaked; few calls total)
    cudaStream_t s2;
    cudaEvent_t evRoot, evB;
    cudaStreamCreateWithFlags(&s2, cudaStreamNonBlocking);
    cudaEventCreateWithFlags(&evRoot, cudaEventDisableTiming);
    cudaEventCreateWithFlags(&evB, cudaEventDisableTiming);

    cudaEventRecord(evRoot, 0);
    cudaStreamWaitEvent(s2, evRoot, 0);

    // --- main stream: encode -> pack -> GEMM1 (gemm is 4th submission: profiled) ---
    k_encode<<<N_NODES, 128>>>(des, twt, nump, catp, Wd, bd, Wt, bt, Wn, bn, Wc, bc);
    k_packAll<<<(5 * 16384 + TB - 1) / TB, TB>>>(W_in, W_o1, W_rel, W_root);
    k_zero_seg<<<(NR + TB - 1) / TB, TB, 0, s2>>>();
    k_gemm_tc<<<gGemm, 256>>>(X0h, 128, X0h, 128, 128, 128, WinTh,
                              X1, X1h, N_NODES, b_in, 1, nullptr, nullptr, nullptr);

    // --- side stream: CSR build (overlaps the above) ---
    k_detect<<<1, 64, 0, s2>>>((const unsigned int*)ei, (const unsigned int*)et);
    k_convert_hist<<<ceb, TB, 0, s2>>>(ei, et);
    k_scan1<<<SCAN_NB, 256, 0, s2>>>();
    k_scan2<<<1, 256, 0, s2>>>();
    k_scan3<<<SCAN_NB, 256, 0, s2>>>();
    k_fill<<<ceb, TB, 0, s2>>>();
    cudaEventRecord(evB, s2);
    cudaStreamWaitEvent(0, evB, 0);

    // RGCN layer 1: Mh = means(X1); X2 = [Mh|X1h] @ WstkT^T + b_rg
    k_agg2<<<gAgg, TB>>>(X1, Mh);
    k_gemm_tc<<<gGemm, 256>>>(Mh, 256, X1h, 128, 256, 384, WstkTh,
                              X2, X2h, N_NODES, b_rg, 0, nullptr, nullptr, nullptr);

    // RGCN layer 2: Mh = means(X2); X3h = [Mh|X2h] @ WstkT^T + b_rg (fp16 only)
    k_agg2<<<gAgg, TB>>>(X2, Mh);
    k_gemm_tc<<<gGemm, 256>>>(Mh, 256, X2h, 128, 256, 384, WstkTh,
                              nullptr, X3h, N_NODES, b_rg, 0, nullptr, nullptr, nullptr);

    // fused: out = lrelu(X3 @ Wo1 + b_o1) @ W_o2 + b_o2
    k_gemm_tc<<<gGemm, 256>>>(X3h, 128, X3h, 128, 128, 128, Wo1Th,
                              nullptr, nullptr, N_NODES, b_o1, 1, W_o2, b_o2, out);
}

// round 11
// speedup vs baseline: 2.9420x; 1.0891x over previous
#include <cuda_runtime.h>
#include <cuda_fp16.h>
#include <cstdint>

#define N_NODES 100000
#define N_EDGES 1600000
#define D 128
#define R 2
#define NR (N_NODES * R)          // 200000 segments
#define SCAN_CHUNK 1024
#define SCAN_NB ((NR + SCAN_CHUNK - 1) / SCAN_CHUNK)   // 196

// ----------------------------- scratch (static device globals; no allocs) ---
__device__ __half g_X0h[(size_t)N_NODES * D];    // encoder out (fp16)
__device__ __half g_X1h[(size_t)N_NODES * D];    // gemm1 out (fp16)
__device__ __half g_X2h[(size_t)N_NODES * D];    // gemm2 out (fp16)
__device__ __half g_X3h[(size_t)N_NODES * D];    // gemm3 out (fp16)
__device__ __half g_Mh [(size_t)N_NODES * 256];  // [mean_rel0 | mean_rel1] fp16
__device__ __half g_WinTh[D * D];
__device__ __half g_Wo1Th[D * D];
__device__ __half g_WstkTh[D * 384];
__device__ int   g_src[N_EDGES];
__device__ int   g_dst[N_EDGES];
__device__ int   g_typ[N_EDGES];
__device__ int   g_cnt[NR];
__device__ int   g_fill[NR];
__device__ int   g_rs[NR + 1];
__device__ int   g_bsums[256];
__device__ int   g_flag[2];
__device__ int   g_csr[N_EDGES];

// ----------------------------- dtype detection -----------------------------
__global__ void k_detect(const unsigned int* __restrict__ ei,
                         const unsigned int* __restrict__ et) {
    __shared__ int nz_i, nz_t;
    if (threadIdx.x == 0) { nz_i = 0; nz_t = 0; }
    __syncthreads();
    for (int i = threadIdx.x; i < 512; i += blockDim.x) {
        if (ei[2 * i + 1] != 0u) atomicOr(&nz_i, 1);
        if (et[2 * i + 1] != 0u) atomicOr(&nz_t, 1);
    }
    __syncthreads();
    if (threadIdx.x == 0) {
        g_flag[0] = (nz_i == 0) ? 1 : 0;
        g_flag[1] = (nz_t == 0) ? 1 : 0;
    }
}

// convert + histogram in one pass over the edge list
__global__ void k_convert_hist(const void* __restrict__ ei, const void* __restrict__ et) {
    int i = blockIdx.x * blockDim.x + threadIdx.x;
    if (i >= N_EDGES) return;
    int s, d, t;
    if (g_flag[0]) {
        const long long* p = (const long long*)ei;
        s = (int)p[i]; d = (int)p[(size_t)N_EDGES + i];
    } else {
        const int* p = (const int*)ei;
        s = p[i]; d = p[N_EDGES + i];
    }
    if (g_flag[1]) t = (int)((const long long*)et)[i];
    else           t = ((const int*)et)[i];
    g_src[i] = s; g_dst[i] = d; g_typ[i] = t;
    atomicAdd(&g_cnt[d * R + t], 1);
}

// ----------------------------- CSR build -----------------------------------
__global__ void k_zero_seg() {
    int i = blockIdx.x * blockDim.x + threadIdx.x;
    if (i < NR) { g_cnt[i] = 0; g_fill[i] = 0; }
}

__global__ void k_scan1() {
    __shared__ int sh[256];
    int b = blockIdx.x, t = threadIdx.x;
    int s = 0;
    #pragma unroll
    for (int i = 0; i < 4; i++) {
        int idx = b * SCAN_CHUNK + t * 4 + i;
        if (idx < NR) s += g_cnt[idx];
    }
    sh[t] = s; __syncthreads();
    for (int off = 128; off > 0; off >>= 1) {
        if (t < off) sh[t] += sh[t + off];
        __syncthreads();
    }
    if (t == 0) g_bsums[b] = sh[0];
}

__global__ void k_scan2() {
    __shared__ int sh[256];
    int t = threadIdx.x;
    sh[t] = (t < SCAN_NB) ? g_bsums[t] : 0;
    __syncthreads();
    if (t == 0) {
        int run = 0;
        for (int i = 0; i < SCAN_NB; i++) { int c = sh[i]; sh[i] = run; run += c; }
        g_rs[NR] = N_EDGES;
    }
    __syncthreads();
    if (t < SCAN_NB) g_bsums[t] = sh[t];
}

__global__ void k_scan3() {
    __shared__ int sh[256];
    int b = blockIdx.x, t = threadIdx.x;
    int base = b * SCAN_CHUNK;
    int v[4]; int s = 0;
    #pragma unroll
    for (int i = 0; i < 4; i++) {
        int idx = base + t * 4 + i;
        v[i] = (idx < NR) ? g_cnt[idx] : 0;
        s += v[i];
    }
    sh[t] = s; __syncthreads();
    for (int off = 1; off < 256; off <<= 1) {
        int cur = sh[t];
        int y = (t >= off) ? sh[t - off] : 0;
        __syncthreads();
        sh[t] = cur + y;
        __syncthreads();
    }
    int run = g_bsums[b] + sh[t] - s;
    #pragma unroll
    for (int i = 0; i < 4; i++) {
        int idx = base + t * 4 + i;
        if (idx < NR) g_rs[idx] = run;
        run += v[i];
    }
}

__global__ void k_fill() {
    int i = blockIdx.x * blockDim.x + threadIdx.x;
    if (i >= N_EDGES) return;
    int seg = g_dst[i] * R + g_typ[i];
    int pos = atomicAdd(&g_fill[seg], 1);
    g_csr[g_rs[seg] + pos] = g_src[i];
}

// ----------------------------- feature encoder (fp16 out) ------------------
__global__ void k_encode(const float* __restrict__ des, const float* __restrict__ twt,
                         const float* __restrict__ nump, const float* __restrict__ catp,
                         const float* __restrict__ Wd, const float* __restrict__ bd,
                         const float* __restrict__ Wt, const float* __restrict__ bt,
                         const float* __restrict__ Wn, const float* __restrict__ bn,
                         const float* __restrict__ Wc, const float* __restrict__ bc) {
    int n = blockIdx.x;
    __shared__ float sin[224];
    int t = threadIdx.x;
    if (t < 100) sin[t] = des[(size_t)n * 100 + t];
    for (int i = t; i < 100; i += 128) sin[100 + i] = twt[(size_t)n * 100 + i];
    if (t < 6)  sin[200 + t] = nump[(size_t)n * 6 + t];
    if (t < 11) sin[206 + t] = catp[(size_t)n * 11 + t];
    __syncthreads();

    int q = t >> 5, j = t & 31;
    const float* W; const float* b; const float* in; int fan;
    if (q == 0)      { W = Wd; b = bd; in = sin;       fan = 100; }
    else if (q == 1) { W = Wt; b = bt; in = sin + 100; fan = 100; }
    else if (q == 2) { W = Wn; b = bn; in = sin + 200; fan = 6;   }
    else             { W = Wc; b = bc; in = sin + 206; fan = 11;  }
    float acc = b[j];
    for (int k = 0; k < fan; k++) acc = fmaf(in[k], W[k * 32 + j], acc);
    acc = acc > 0.f ? acc : 0.01f * acc;
    g_X0h[(size_t)n * D + t] = __float2half_rn(acc);
}

// ----------------------------- weight pack (fp16 transposed) ---------------
__global__ void k_packAll(const float* __restrict__ W_in, const float* __restrict__ W_o1,
                          const float* __restrict__ W_rel, const float* __restrict__ W_root) {
    int i = blockIdx.x * blockDim.x + threadIdx.x;
    if (i >= 5 * 16384) return;
    int reg = i >> 14, r = i & 16383;
    int k = r >> 7, n = r & 127;
    if (reg == 0)      g_WinTh[n * 128 + k] = __float2half_rn(W_in[r]);
    else if (reg == 1) g_Wo1Th[n * 128 + k] = __float2half_rn(W_o1[r]);
    else if (reg == 2) g_WstkTh[n * 384 + k]       = __float2half_rn(W_rel[r]);
    else if (reg == 3) g_WstkTh[n * 384 + 128 + k] = __float2half_rn(W_rel[16384 + r]);
    else               g_WstkTh[n * 384 + 256 + k] = __float2half_rn(W_root[r]);
}

// ----------------------------- fp16 mma GEMM: 3-stage cp.async + ldmatrix --
// Ch[M,128] = A[M,kTot] @ Bt[128,kTot]^T + bias (optional lrelu), or fused
// final projection (out2 != nullptr). 256 threads, tile 128x128, 8 warps
// 4(m)x2(n), K-slab 32, 3-stage cp.async pipeline, 80B row stride.

#define RS 40                      // smem row stride in halfs
#define A_BYTES (128 * RS * 2)     // 10240 per matrix per stage
#define STAGE_BYTES (2 * A_BYTES)  // 20480 (A + B)
#define SMEM_TOT (3 * STAGE_BYTES) // 61440

__device__ __forceinline__ unsigned f2h2(float lo, float hi) {
    unsigned r;
    asm("cvt.rn.f16x2.f32 %0, %1, %2;" : "=r"(r) : "f"(hi), "f"(lo));
    return r;
}

__device__ __forceinline__ void cpa16(uint32_t dst, const void* src) {
    asm volatile("cp.async.cg.shared.global [%0], [%1], 16;" :: "r"(dst), "l"(src));
}

__device__ __forceinline__ void mma_f16(float* c, const unsigned* a,
                                        unsigned b0, unsigned b1) {
    asm volatile(
        "mma.sync.aligned.m16n8k16.row.col.f32.f16.f16.f32 "
        "{%0,%1,%2,%3}, {%4,%5,%6,%7}, {%8,%9}, {%0,%1,%2,%3};"
        : "+f"(c[0]), "+f"(c[1]), "+f"(c[2]), "+f"(c[3])
        : "r"(a[0]), "r"(a[1]), "r"(a[2]), "r"(a[3]), "r"(b0), "r"(b1));
}

__device__ __forceinline__ void stage_slab(
    uint32_t sAb, uint32_t sBb,
    const __half* __restrict__ A1, int ldA1,
    const __half* __restrict__ A2, int ldA2, int kSplit,
    const __half* __restrict__ Bt, int kTot,
    int k0, int bm, int M, int tid)
{
    #pragma unroll
    for (int i = 0; i < 2; i++) {
        int c = tid + i * 256;            // 0..511
        int row = c >> 2, ch = c & 3;
        int grow = bm + row; if (grow > M - 1) grow = M - 1;
        const __half* src = (k0 < kSplit)
            ? A1 + (size_t)grow * ldA1 + k0 + ch * 8
            : A2 + (size_t)grow * ldA2 + (k0 - kSplit) + ch * 8;
        cpa16(sAb + (row * RS + ch * 8) * 2, src);
    }
    #pragma unroll
    for (int i = 0; i < 2; i++) {
        int c = tid + i * 256;
        int row = c >> 2, ch = c & 3;
        const __half* src = Bt + (size_t)row * kTot + k0 + ch * 8;
        cpa16(sBb + (row * RS + ch * 8) * 2, src);
    }
    asm volatile("cp.async.commit_group;");
}

__global__ __launch_bounds__(256) void k_gemm_tc(
    const __half* __restrict__ A1, int ldA1,
    const __half* __restrict__ A2, int ldA2,
    int kSplit, int kTot,
    const __half* __restrict__ Bt,
    __half* __restrict__ Ch, int M,
    const float* __restrict__ bias, int act,
    const float* __restrict__ Wo2, const float* __restrict__ bo2,
    float* __restrict__ out2)
{
    extern __shared__ char dynsmem[];
    uint32_t smem0 = (uint32_t)__cvta_generic_to_shared(dynsmem);

    int tid = threadIdx.x;
    int wid = tid >> 5, lane = tid & 31;
    int gid = lane >> 2, tig = lane & 3;
    int lg = lane >> 3, lr = lane & 7;
    int warp_m = wid & 3, warp_n = wid >> 2;
    int bm = blockIdx.x * 128;

    float acc[2][8][4];
    #pragma unroll
    for (int i = 0; i < 2; i++)
        #pragma unroll
        for (int j = 0; j < 8; j++)
            #pragma unroll
            for (int q = 0; q < 4; q++) acc[i][j][q] = 0.f;

    int nSlab = kTot >> 5;
    stage_slab(smem0, smem0 + A_BYTES, A1, ldA1, A2, ldA2, kSplit, Bt, kTot, 0, bm, M, tid);
    if (nSlab > 1)
        stage_slab(smem0 + STAGE_BYTES, smem0 + STAGE_BYTES + A_BYTES,
                   A1, ldA1, A2, ldA2, kSplit, Bt, kTot, 32, bm, M, tid);

    for (int s = 0; s < nSlab; s++) {
        if (s + 1 < nSlab) asm volatile("cp.async.wait_group 1;");
        else               asm volatile("cp.async.wait_group 0;");
        __syncthreads();
        if (s + 2 < nSlab) {
            uint32_t nb = smem0 + (uint32_t)((s + 2) % 3) * STAGE_BYTES;
            stage_slab(nb, nb + A_BYTES, A1, ldA1, A2, ldA2, kSplit, Bt, kTot,
                       (s + 2) << 5, bm, M, tid);
        }
        uint32_t sAb = smem0 + (uint32_t)(s % 3) * STAGE_BYTES;
        uint32_t sBb = sAb + A_BYTES;

        #pragma unroll
        for (int kk = 0; kk < 2; kk++) {
            unsigned af[2][4];
            #pragma unroll
            for (int mf = 0; mf < 2; mf++) {
                int row = warp_m * 32 + mf * 16 + ((lg & 1) << 3) + lr;
                int col = (kk << 4) + ((lg >> 1) << 3);
                uint32_t ad = sAb + (uint32_t)(row * RS + col) * 2;
                asm volatile(
                    "ldmatrix.sync.aligned.m8n8.x4.shared.b16 {%0,%1,%2,%3}, [%4];"
                    : "=r"(af[mf][0]), "=r"(af[mf][1]), "=r"(af[mf][2]), "=r"(af[mf][3])
                    : "r"(ad));
            }
            #pragma unroll
            for (int np = 0; np < 4; np++) {
                int row = warp_n * 64 + np * 16 + ((lg >> 1) << 3) + lr;
                int col = (kk << 4) + ((lg & 1) << 3);
                uint32_t bd = sBb + (uint32_t)(row * RS + col) * 2;
                unsigned b0, b1, b2, b3;
                asm volatile(
                    "ldmatrix.sync.aligned.m8n8.x4.shared.b16 {%0,%1,%2,%3}, [%4];"
                    : "=r"(b0), "=r"(b1), "=r"(b2), "=r"(b3) : "r"(bd));
                mma_f16(acc[0][2 * np],     af[0], b0, b1);
                mma_f16(acc[1][2 * np],     af[1], b0, b1);
                mma_f16(acc[0][2 * np + 1], af[0], b2, b3);
                mma_f16(acc[1][2 * np + 1], af[1], b2, b3);
            }
        }
    }

    if (out2 == nullptr) {
        // ---- epilogue: bias (+lrelu), store fp16 Ch ----
        #pragma unroll
        for (int mf = 0; mf < 2; mf++) {
            int r0 = bm + warp_m * 32 + mf * 16 + gid;
            int r1 = r0 + 8;
            #pragma unroll
            for (int nf = 0; nf < 8; nf++) {
                int c = warp_n * 64 + nf * 8 + tig * 2;
                float b0 = bias[c], b1 = bias[c + 1];
                float v0 = acc[mf][nf][0] + b0, v1 = acc[mf][nf][1] + b1;
                float v2 = acc[mf][nf][2] + b0, v3 = acc[mf][nf][3] + b1;
                if (act) {
                    v0 = v0 > 0.f ? v0 : 0.01f * v0;
                    v1 = v1 > 0.f ? v1 : 0.01f * v1;
                    v2 = v2 > 0.f ? v2 : 0.01f * v2;
                    v3 = v3 > 0.f ? v3 : 0.01f * v3;
                }
                if (r0 < M) *(unsigned*)(Ch + (size_t)r0 * 128 + c) = f2h2(v0, v1);
                if (r1 < M) *(unsigned*)(Ch + (size_t)r1 * 128 + c) = f2h2(v2, v3);
            }
        }
    } else {
        // ---- fused final projection: out2[r] = lrelu(C_row+bias) @ Wo2 + bo2 ----
        float p[2][2][2] = {{{0.f,0.f},{0.f,0.f}},{{0.f,0.f},{0.f,0.f}}};
        #pragma unroll
        for (int mf = 0; mf < 2; mf++) {
            #pragma unroll
            for (int nf = 0; nf < 8; nf++) {
                int c = warp_n * 64 + nf * 8 + tig * 2;
                float b0 = bias[c], b1 = bias[c + 1];
                float v0 = acc[mf][nf][0] + b0, v1 = acc[mf][nf][1] + b1;
                float v2 = acc[mf][nf][2] + b0, v3 = acc[mf][nf][3] + b1;
                if (act) {
                    v0 = v0 > 0.f ? v0 : 0.01f * v0;
                    v1 = v1 > 0.f ? v1 : 0.01f * v1;
                    v2 = v2 > 0.f ? v2 : 0.01f * v2;
                    v3 = v3 > 0.f ? v3 : 0.01f * v3;
                }
                float w00 = Wo2[c * 2 + 0], w01 = Wo2[c * 2 + 1];
                float w10 = Wo2[c * 2 + 2], w11 = Wo2[c * 2 + 3];
                p[mf][0][0] = fmaf(v0, w00, fmaf(v1, w10, p[mf][0][0]));
                p[mf][0][1] = fmaf(v0, w01, fmaf(v1, w11, p[mf][0][1]));
                p[mf][1][0] = fmaf(v2, w00, fmaf(v3, w10, p[mf][1][0]));
                p[mf][1][1] = fmaf(v2, w01, fmaf(v3, w11, p[mf][1][1]));
            }
        }
        #pragma unroll
        for (int m = 1; m < 4; m <<= 1) {
            #pragma unroll
            for (int mf = 0; mf < 2; mf++)
                #pragma unroll
                for (int h = 0; h < 2; h++)
                    #pragma unroll
                    for (int j = 0; j < 2; j++)
                        p[mf][h][j] += __shfl_xor_sync(0xFFFFFFFFu, p[mf][h][j], m);
        }
        __syncthreads();
        float* sRed = (float*)dynsmem;   // 256 floats reused
        if (warp_n == 0 && tig == 0) {
            #pragma unroll
            for (int mf = 0; mf < 2; mf++)
                #pragma unroll
                for (int h = 0; h < 2; h++) {
                    int rid = warp_m * 32 + mf * 16 + h * 8 + gid;
                    sRed[rid * 2 + 0] = p[mf][h][0];
                    sRed[rid * 2 + 1] = p[mf][h][1];
                }
        }
        __syncthreads();
        if (warp_n == 1 && tig == 0) {
            #pragma unroll
            for (int mf = 0; mf < 2; mf++)
                #pragma unroll
                for (int h = 0; h < 2; h++) {
                    int rid = warp_m * 32 + mf * 16 + h * 8 + gid;
                    int row = bm + rid;
                    if (row < M) {
                        out2[(size_t)row * 2 + 0] = p[mf][h][0] + sRed[rid * 2 + 0] + bo2[0];
                        out2[(size_t)row * 2 + 1] = p[mf][h][1] + sRed[rid * 2 + 1] + bo2[1];
                    }
                }
        }
    }
}

// ----------------------------- aggregation (fp16 in, fp16 means out) -------
// one warp per (node,rel); 256B rows, uint2 per lane (4 halfs), fp32 accum
__global__ void k_agg2(const __half* __restrict__ Xh, __half* __restrict__ Mh) {
    int w = (blockIdx.x * blockDim.x + threadIdx.x) >> 5;
    if (w >= NR) return;
    int lane = threadIdx.x & 31;
    int n = w >> 1, rel = w & 1;
    int s = g_rs[w], e = g_rs[w + 1];
    float s0 = 0.f, s1 = 0.f, s2 = 0.f, s3 = 0.f;
    int i = s;
    for (; i + 4 <= e; i += 4) {
        int i0 = g_csr[i], i1 = g_csr[i + 1], i2 = g_csr[i + 2], i3 = g_csr[i + 3];
        uint2 a = ((const uint2*)(Xh + (size_t)i0 * D))[lane];
        uint2 b = ((const uint2*)(Xh + (size_t)i1 * D))[lane];
        uint2 c = ((const uint2*)(Xh + (size_t)i2 * D))[lane];
        uint2 d = ((const uint2*)(Xh + (size_t)i3 * D))[lane];
        float2 f;
        f = __half22float2(*(__half2*)&a.x); s0 += f.x; s1 += f.y;
        f = __half22float2(*(__half2*)&a.y); s2 += f.x; s3 += f.y;
        f = __half22float2(*(__half2*)&b.x); s0 += f.x; s1 += f.y;
        f = __half22float2(*(__half2*)&b.y); s2 += f.x; s3 += f.y;
        f = __half22float2(*(__half2*)&c.x); s0 += f.x; s1 += f.y;
        f = __half22float2(*(__half2*)&c.y); s2 += f.x; s3 += f.y;
        f = __half22float2(*(__half2*)&d.x); s0 += f.x; s1 += f.y;
        f = __half22float2(*(__half2*)&d.y); s2 += f.x; s3 += f.y;
    }
    for (; i < e; i++) {
        uint2 a = ((const uint2*)(Xh + (size_t)g_csr[i] * D))[lane];
        float2 f;
        f = __half22float2(*(__half2*)&a.x); s0 += f.x; s1 += f.y;
        f = __half22float2(*(__half2*)&a.y); s2 += f.x; s3 += f.y;
    }
    float inv = (e > s) ? 1.0f / (float)(e - s) : 0.0f;
    unsigned u0 = f2h2(s0 * inv, s1 * inv), u1 = f2h2(s2 * inv, s3 * inv);
    *(uint2*)(Mh + (size_t)n * 256 + rel * D + lane * 4) = make_uint2(u0, u1);
}

// ----------------------------- launch --------------------------------------
extern "C" void kernel_launch(void* const* d_in, const int* in_sizes, int n_in,
                              void* d_out, int out_size) {
    const float* des   = (const float*)d_in[0];
    const float* twt   = (const float*)d_in[1];
    const float* nump  = (const float*)d_in[2];
    const float* catp  = (const float*)d_in[3];
    const void*  ei    = d_in[4];
    const void*  et    = d_in[5];
    const float* Wd    = (const float*)d_in[6];
    const float* bd    = (const float*)d_in[7];
    const float* Wt    = (const float*)d_in[8];
    const float* bt    = (const float*)d_in[9];
    const float* Wn    = (const float*)d_in[10];
    const float* bn    = (const float*)d_in[11];
    const float* Wc    = (const float*)d_in[12];
    const float* bc    = (const float*)d_in[13];
    const float* W_in  = (const float*)d_in[14];
    const float* b_in  = (const float*)d_in[15];
    const float* W_rel = (const float*)d_in[16];
    const float* W_root= (const float*)d_in[17];
    const float* b_rg  = (const float*)d_in[18];
    const float* W_o1  = (const float*)d_in[19];
    const float* b_o1  = (const float*)d_in[20];
    const float* W_o2  = (const float*)d_in[21];
    const float* b_o2  = (const float*)d_in[22];
    float* out = (float*)d_out;

    __half *X0h, *X1h, *X2h, *X3h, *Mh, *WinTh, *Wo1Th, *WstkTh;
    cudaGetSymbolAddress((void**)&X0h, g_X0h);
    cudaGetSymbolAddress((void**)&X1h, g_X1h);
    cudaGetSymbolAddress((void**)&X2h, g_X2h);
    cudaGetSymbolAddress((void**)&X3h, g_X3h);
    cudaGetSymbolAddress((void**)&Mh,  g_Mh);
    cudaGetSymbolAddress((void**)&WinTh,  g_WinTh);
    cudaGetSymbolAddress((void**)&Wo1Th,  g_Wo1Th);
    cudaGetSymbolAddress((void**)&WstkTh, g_WstkTh);

    cudaFuncSetAttribute(k_gemm_tc, cudaFuncAttributeMaxDynamicSharedMemorySize, SMEM_TOT);

    const int TB = 256;
    int ceb = (N_EDGES + TB - 1) / TB;
    int gGemm = (N_NODES + 127) / 128;      // 782
    int gAgg  = (NR * 32 + TB - 1) / TB;    // 25000

    // side stream for the independent CSR-build chain (leaked; few calls total)
    cudaStream_t s2;
    cudaEvent_t evRoot, evB;
    cudaStreamCreateWithFlags(&s2, cudaStreamNonBlocking);
    cudaEventCreateWithFlags(&evRoot, cudaEventDisableTiming);
    cudaEventCreateWithFlags(&evB, cudaEventDisableTiming);

    cudaEventRecord(evRoot, 0);
    cudaStreamWaitEvent(s2, evRoot, 0);

    // --- main stream: encode -> pack -> GEMM1 (gemm is 4th submission: profiled) ---
    k_encode<<<N_NODES, 128>>>(des, twt, nump, catp, Wd, bd, Wt, bt, Wn, bn, Wc, bc);
    k_packAll<<<(5 * 16384 + TB - 1) / TB, TB>>>(W_in, W_o1, W_rel, W_root);
    k_zero_seg<<<(NR + TB - 1) / TB, TB, 0, s2>>>();
    k_gemm_tc<<<gGemm, 256, SMEM_TOT>>>(X0h, 128, X0h, 128, 128, 128, WinTh,
                                        X1h, N_NODES, b_in, 1, nullptr, nullptr, nullptr);

    // --- side stream: CSR build (overlaps the above) ---
    k_detect<<<1, 64, 0, s2>>>((const unsigned int*)ei, (const unsigned int*)et);
    k_convert_hist<<<ceb, TB, 0, s2>>>(ei, et);
    k_scan1<<<SCAN_NB, 256, 0, s2>>>();
    k_scan2<<<1, 256, 0, s2>>>();
    k_scan3<<<SCAN_NB, 256, 0, s2>>>();
    k_fill<<<ceb, TB, 0, s2>>>();
    cudaEventRecord(evB, s2);
    cudaStreamWaitEvent(0, evB, 0);

    // RGCN layer 1: Mh = means(X1h); X2h = [Mh|X1h] @ WstkT^T + b_rg
    k_agg2<<<gAgg, TB>>>(X1h, Mh);
    k_gemm_tc<<<gGemm, 256, SMEM_TOT>>>(Mh, 256, X1h, 128, 256, 384, WstkTh,
                                        X2h, N_NODES, b_rg, 0, nullptr, nullptr, nullptr);

    // RGCN layer 2: Mh = means(X2h); X3h = [Mh|X2h] @ WstkT^T + b_rg
    k_agg2<<<gAgg, TB>>>(X2h, Mh);
    k_gemm_tc<<<gGemm, 256, SMEM_TOT>>>(Mh, 256, X2h, 128, 256, 384, WstkTh,
                                        X3h, N_NODES, b_rg, 0, nullptr, nullptr, nullptr);

    // fused: out = lrelu(X3 @ Wo1 + b_o1) @ W_o2 + b_o2
    k_gemm_tc<<<gGemm, 256, SMEM_TOT>>>(X3h, 128, X3h, 128, 128, 128, Wo1Th,
                                        nullptr, N_NODES, b_o1, 1, W_o2, b_o2, out);
}